// round 10
// baseline (speedup 1.0000x reference)
#include <cuda_runtime.h>
#include <cuda_bf16.h>
#include <math.h>

#define B   64
#define C   512
#define CP  128
#define HH  32
#define WW  32
#define HW  1024
#define NSEL (B*CP*HW)       // 8388608
#define NALL (B*C*HW)        // 33554432
#define NSLOT 11

// ---------------- scratch (device globals; no allocs allowed) ----------------
__device__ float g_ca[B*C];
__device__ int   g_idx[CP];
__device__ float g_xtemp[NSEL];
__device__ float g_t1[NSEL];
__device__ float g_t2[NSEL];
__device__ float g_bmax[NSEL];
__device__ float g_bavg[NSEL];
__device__ float g_s3[NSEL];
__device__ float g_s5[NSEL];
__device__ float g_s7[NSEL];
__device__ float g_d3[NSEL];
__device__ float g_d5[NSEL];
__device__ float g_c7[NSEL];
__device__ double g_ssum [NSLOT*CP];
__device__ double g_ssum2[NSLOT*CP];
__device__ float  g_meanv[NSLOT*CP];
__device__ float  g_rstdv[NSLOT*CP];

// slots: 0 max, 1 avg, 2 sep3mid, 3 sep3fin, 4 sep5mid, 5 sep5fin,
//        6 sep7mid, 7 sep7fin, 8 dil3, 9 dil5, 10 c7

typedef unsigned long long ull;
__device__ __forceinline__ ull pack2(float a, float b){
    ull r; asm("mov.b64 %0,{%1,%2};":"=l"(r):"f"(a),"f"(b)); return r;
}
__device__ __forceinline__ void unpack2(ull v, float&a, float&b){
    asm("mov.b64 {%0,%1},%2;":"=f"(a),"=f"(b):"l"(v));
}
__device__ __forceinline__ void ffma2(ull&d, ull a, ull b){
    asm("fma.rn.f32x2 %0,%1,%2,%0;":"+l"(d):"l"(a),"l"(b));
}

// ---------------- 0. fused global pooling + attention MLP (+ stats zero) -----
__global__ void __launch_bounds__(512) attn_fused_kernel(
        const float* __restrict__ x, const float* __restrict__ fc1,
        const float* __restrict__ wa, const float* __restrict__ fc2) {
    int b = blockIdx.x, tid = threadIdx.x;     // 512 threads
    __shared__ float pooled[1024];             // [avg 512 | max 512]
    __shared__ float red[16];
    __shared__ float s_y[10], s_A[100], s_y2[10];
    if (b == 0) {
        for (int i = tid; i < NSLOT*CP; i += 512) { g_ssum[i] = 0.0; g_ssum2[i] = 0.0; }
    }
    int w = tid >> 5, l = tid & 31;
    for (int j = 0; j < 32; j++) {
        int c = w*32 + j;
        const float* p = x + ((size_t)(b*C + c) << 10);
        float s = 0.f, m = -INFINITY;
        #pragma unroll 4
        for (int k = 0; k < 32; k++) { float v = p[l + 32*k]; s += v; m = fmaxf(m, v); }
        #pragma unroll
        for (int o = 16; o > 0; o >>= 1) {
            s += __shfl_xor_sync(0xffffffffu, s, o);
            m = fmaxf(m, __shfl_xor_sync(0xffffffffu, m, o));
        }
        if (l == 0) { pooled[c] = s * (1.f/1024.f); pooled[C + c] = m; }
    }
    __syncthreads();
    for (int j = 0; j < 10; j++) {
        float local = pooled[tid] * fc1[j*2*C + tid] + pooled[512 + tid] * fc1[j*2*C + 512 + tid];
        #pragma unroll
        for (int o = 16; o > 0; o >>= 1) local += __shfl_xor_sync(0xffffffffu, local, o);
        if (l == 0) red[w] = local;
        __syncthreads();
        if (tid == 0) { float t = 0.f; for (int q = 0; q < 16; q++) t += red[q]; s_y[j] = t; }
        __syncthreads();
    }
    if (tid < 100) {
        int j = tid / 10, k = tid % 10;
        float a = 0.f;
        for (int m = 0; m < 14; m++) a += wa[m*10 + j] * wa[m*10 + k];
        s_A[tid] = a;
    }
    __syncthreads();
    if (tid < 10) {
        float v = 0.f;
        for (int k = 0; k < 10; k++) v += s_y[k] * s_A[tid*10 + k];
        s_y2[tid] = fmaxf(v, 0.f);
    }
    __syncthreads();
    {
        int c = tid;
        float v = 0.f;
        for (int j = 0; j < 10; j++) v += s_y2[j] * fc2[c*10 + j];
        g_ca[b*C + c] = 1.f / (1.f + expf(-v));
    }
}

// ---------------- 1. slist + exact lax.top_k ordering (merged) ----------------
__global__ void slist_topk_kernel() {
    __shared__ float v[C];
    int c = threadIdx.x;                       // 512
    float s = 0.f;
    for (int b = 0; b < B; b++) s += g_ca[b*C + c];
    v[c] = s; __syncthreads();
    float mv = v[c];
    int rank = 0;
    for (int i = 0; i < C; i++) {
        float o = v[i];
        rank += (o > mv) || (o == mv && i < c);
    }
    if (rank < CP) g_idx[rank] = c;
}

// ---------------- 2. gather xtemp = (x*ca)[:, idx] (float4) ----------------
__global__ void gather4_kernel(const float* __restrict__ x) {
    int n4 = blockIdx.x * 256 + threadIdx.x;   // < NSEL/4
    int n = n4 << 2;
    int b = n >> 17, p = (n >> 10) & 127, hw = n & 1023;
    int cs = g_idx[p];
    float ca = g_ca[b*C + cs];
    float4 v = *(const float4*)&x[(((size_t)b*C + cs) << 10) + hw];
    v.x *= ca; v.y *= ca; v.z *= ca; v.w *= ca;
    *(float4*)&g_xtemp[n] = v;
}

// ---------------- scale x by ca into d_out (float4) ----------------
__global__ void scale4_kernel(const float* __restrict__ x, float* __restrict__ out) {
    int n4 = blockIdx.x * 256 + threadIdx.x;   // < NALL/4
    int n = n4 << 2;
    float ca = g_ca[n >> 10];
    float4 v = *(const float4*)&x[n];
    v.x *= ca; v.y *= ca; v.z *= ca; v.w *= ca;
    *(float4*)&out[n] = v;
}

// ---------------- fused 3x3 max+avg pool + stats (smem tile) ----------------
__global__ void __launch_bounds__(256) pool3f_kernel(const float* __restrict__ in,
                                                     float* __restrict__ omax,
                                                     float* __restrict__ oavg) {
    __shared__ float s[34][35];
    __shared__ float rsm[8][4];
    int bc = blockIdx.x;
    int tid = threadIdx.x;
    const float* ip = in + ((size_t)bc << 10);
    for (int i = tid; i < 34*34; i += 256) {
        int r = i / 34, q = i - r*34;
        int y = r - 1, x = q - 1;
        s[r][q] = (y >= 0 && y < 32 && x >= 0 && x < 32) ? ip[y*32 + x] : 0.f;
    }
    __syncthreads();
    int y = tid >> 3, x0 = (tid & 7) * 4;
    float vmax[4], vavg[4];
    int yl = (y > 0 ? y-1 : 0), yhh = (y < 31 ? y+1 : 31);
    int ch = yhh - yl + 1;
    #pragma unroll
    for (int t = 0; t < 4; t++) {
        int x = x0 + t;
        float m = -INFINITY, sm = 0.f;
        #pragma unroll
        for (int dy = 0; dy < 3; dy++) {
            int yy = y + dy;
            bool yok = (yy >= 1 && yy <= 32);
            #pragma unroll
            for (int dx = 0; dx < 3; dx++) {
                int xx = x + dx;
                float v = s[yy][xx];
                sm += v;
                if (yok && xx >= 1 && xx <= 32) m = fmaxf(m, v);
            }
        }
        int xl = (x > 0 ? x-1 : 0), xh = (x < 31 ? x+1 : 31);
        int cnt = ch * (xh - xl + 1);
        vmax[t] = m; vavg[t] = sm / (float)cnt;
    }
    size_t base = ((size_t)bc << 10) + y*32 + x0;
    *(float4*)&omax[base] = make_float4(vmax[0],vmax[1],vmax[2],vmax[3]);
    *(float4*)&oavg[base] = make_float4(vavg[0],vavg[1],vavg[2],vavg[3]);
    float sM=0,sM2=0,sA=0,sA2=0;
    #pragma unroll
    for (int t = 0; t < 4; t++) { sM += vmax[t]; sM2 += vmax[t]*vmax[t]; sA += vavg[t]; sA2 += vavg[t]*vavg[t]; }
    #pragma unroll
    for (int o = 16; o > 0; o >>= 1) {
        sM  += __shfl_xor_sync(0xffffffffu, sM,  o);
        sM2 += __shfl_xor_sync(0xffffffffu, sM2, o);
        sA  += __shfl_xor_sync(0xffffffffu, sA,  o);
        sA2 += __shfl_xor_sync(0xffffffffu, sA2, o);
    }
    int w = tid >> 5;
    if ((tid & 31) == 0) { rsm[w][0]=sM; rsm[w][1]=sM2; rsm[w][2]=sA; rsm[w][3]=sA2; }
    __syncthreads();
    if (tid == 0) {
        float a=0,b2=0,c2=0,d2=0;
        for (int q = 0; q < 8; q++) { a+=rsm[q][0]; b2+=rsm[q][1]; c2+=rsm[q][2]; d2+=rsm[q][3]; }
        int c = bc & 127;
        atomicAdd(&g_ssum [0*CP + c], (double)a);
        atomicAdd(&g_ssum2[0*CP + c], (double)b2);
        atomicAdd(&g_ssum [1*CP + c], (double)c2);
        atomicAdd(&g_ssum2[1*CP + c], (double)d2);
    }
}

// ---------------- finalize stats ----------------
__global__ void finalize_kernel() {
    int s = blockIdx.x, c = threadIdx.x;       // 11 x 128
    double su = g_ssum[s*CP+c], sq = g_ssum2[s*CP+c];
    double m  = su * (1.0/65536.0);
    double var = sq * (1.0/65536.0) - m*m;
    g_meanv[s*CP+c] = (float)m;
    g_rstdv[s*CP+c] = (float)rsqrt(var + 1e-5);
}

// ---------------- depthwise conv, smem tile; TRANS: 1 relu, 2 bn+relu --------
template<int K, int DIL, int TRANS>
__global__ void __launch_bounds__(256) dw_conv_kernel(const float* __restrict__ in,
                                                      float* __restrict__ out,
                                                      const float* __restrict__ w,
                                                      int islot) {
    constexpr int P  = (DIL==1) ? (K/2) : (K-1);
    constexpr int SW = 32 + 2*P;
    constexpr int SWP = SW + 1;
    constexpr int SPAN = 4 + (K-1)*DIL;
    __shared__ float s[SW][SWP];
    __shared__ float s_mr[2];
    int bc = blockIdx.x;
    int c = bc & 127;
    int tid = threadIdx.x;
    if (TRANS == 2 && tid == 0) {
        double su = g_ssum[islot*CP + c], sq = g_ssum2[islot*CP + c];
        double m = su * (1.0/65536.0);
        double var = sq * (1.0/65536.0) - m*m;
        s_mr[0] = (float)m; s_mr[1] = (float)rsqrt(var + 1e-5);
    }
    if (TRANS == 2) __syncthreads();
    float mean = 0.f, rstd = 1.f;
    if (TRANS == 2) { mean = s_mr[0]; rstd = s_mr[1]; }
    const float* ip = in + ((size_t)bc << 10);
    for (int i = tid; i < SW*SW; i += 256) {
        int r = i / SW, q = i - r*SW;
        int y = r - P, x = q - P;
        float v = 0.f;
        if (y >= 0 && y < 32 && x >= 0 && x < 32) {
            v = ip[y*32 + x];
            if (TRANS == 1) v = fmaxf(v, 0.f);
            else if (TRANS == 2) v = fmaxf((v - mean)*rstd, 0.f);
        }
        s[r][q] = v;
    }
    float wr[K][K];
    #pragma unroll
    for (int i = 0; i < K; i++)
        #pragma unroll
        for (int j = 0; j < K; j++) wr[i][j] = w[(c*K + i)*K + j];
    __syncthreads();
    int y = tid >> 3, x0 = (tid & 7) * 4;
    float acc[4] = {0.f, 0.f, 0.f, 0.f};
    #pragma unroll
    for (int i = 0; i < K; i++) {
        float r[SPAN];
        #pragma unroll
        for (int q = 0; q < SPAN; q++) r[q] = s[y + i*DIL][x0 + q];
        #pragma unroll
        for (int j = 0; j < K; j++)
            #pragma unroll
            for (int t = 0; t < 4; t++) acc[t] = fmaf(wr[i][j], r[j*DIL + t], acc[t]);
    }
    *(float4*)&out[((size_t)bc << 10) + y*32 + x0] = make_float4(acc[0],acc[1],acc[2],acc[3]);
}

// ---------------- pointwise conv 128->128, f32x2, packed weights -------------
// 256 threads; block = 64co x 8y x 32x; thread = 8co x 4y x 2x; warp = co-group
__global__ void __launch_bounds__(256) pw_conv_kernel(const float* __restrict__ in,
                                                      float* __restrict__ out,
                                                      const float* __restrict__ w,
                                                      int oslot) {
    __shared__ __align__(16) float s_in[16][8][32];   // 16 KB
    __shared__ ull s_wp[64][16];                      // (w,w) pairs, 8 KB
    int tid = threadIdx.x;
    int co0 = blockIdx.x * 64, y0 = blockIdx.y * 8, b = blockIdx.z;
    int xp = tid & 15, yh = (tid >> 4) & 1, cg = tid >> 5;
    ull acc[8][4];
    #pragma unroll
    for (int j = 0; j < 8; j++)
        #pragma unroll
        for (int k = 0; k < 4; k++) acc[j][k] = 0ull;

    for (int cc = 0; cc < CP; cc += 16) {
        { int co = tid >> 2, cq = (tid & 3) * 4;
          float4 v = *(const float4*)&w[(size_t)(co0+co)*CP + cc + cq];
          s_wp[co][cq+0] = pack2(v.x, v.x);
          s_wp[co][cq+1] = pack2(v.y, v.y);
          s_wp[co][cq+2] = pack2(v.z, v.z);
          s_wp[co][cq+3] = pack2(v.w, v.w); }
        #pragma unroll
        for (int i = tid; i < 1024; i += 256) {       // float4 units
            int ci = i >> 6, rem = i & 63;
            int y = rem >> 3, h = rem & 7;
            *(float4*)&s_in[ci][y][h*4] =
                *(const float4*)&in[(((size_t)b*CP + cc+ci)*HH + y0+y)*WW + h*4];
        }
        __syncthreads();
        #pragma unroll
        for (int ci = 0; ci < 16; ci++) {
            ull iv[4];
            #pragma unroll
            for (int k = 0; k < 4; k++) iv[k] = *(const ull*)&s_in[ci][yh*4 + k][2*xp];
            #pragma unroll
            for (int j = 0; j < 8; j++) {
                ull wv2 = s_wp[cg*8 + j][ci];
                #pragma unroll
                for (int k = 0; k < 4; k++) ffma2(acc[j][k], wv2, iv[k]);
            }
        }
        __syncthreads();
    }
    #pragma unroll
    for (int j = 0; j < 8; j++) {
        int co = co0 + cg*8 + j;
        float s = 0.f, s2 = 0.f;
        #pragma unroll
        for (int k = 0; k < 4; k++) {
            float v0, v1; unpack2(acc[j][k], v0, v1);
            *(float2*)&out[(((size_t)b*CP + co)*HH + y0 + yh*4 + k)*WW + 2*xp] = make_float2(v0, v1);
            s += v0 + v1; s2 += v0*v0 + v1*v1;
        }
        #pragma unroll
        for (int o = 16; o > 0; o >>= 1) {
            s  += __shfl_xor_sync(0xffffffffu, s,  o);
            s2 += __shfl_xor_sync(0xffffffffu, s2, o);
        }
        if ((tid & 31) == 0 && oslot >= 0) {
            atomicAdd(&g_ssum [oslot*CP + co], (double)s);
            atomicAdd(&g_ssum2[oslot*CP + co], (double)s2);
        }
    }
}

// ---------------- 1x7 conv (KW=7, pad 3), relu-in, x-pair registers ----------
// 256 threads; block = 64co x 8y x 32x; thread = 8co x 1y x 8x (4 pairs)
__global__ void __launch_bounds__(256) conv1x7_kernel(const float* __restrict__ in,
                                                      float* __restrict__ out,
                                                      const float* __restrict__ w) {
    __shared__ float s_in[8][8][40];     // 8ci x 8y x (32+6 pad->40), 10.24 KB
    __shared__ ull s_wp[64][8][7];       // packed (w,w), 28.7 KB
    int tid = threadIdx.x;
    int co0 = blockIdx.x * 64, y0 = blockIdx.y * 8, b = blockIdx.z;
    int sp = tid & 31, cg = tid >> 5;
    int y = sp >> 2, xq = (sp & 3) * 8;
    ull acc[8][4];
    #pragma unroll
    for (int j = 0; j < 8; j++)
        #pragma unroll
        for (int p = 0; p < 4; p++) acc[j][p] = 0ull;

    for (int cc = 0; cc < CP; cc += 8) {
        for (int i = tid; i < 8*8*40; i += 256) {
            int ci = i / 320, rem = i - ci*320;
            int yy = rem / 40, q = rem - yy*40;
            int x = q - 3;
            float v = 0.f;
            if (x >= 0 && x < WW)
                v = fmaxf(in[(((size_t)b*CP + cc+ci)*HH + y0+yy)*WW + x], 0.f);
            s_in[ci][yy][q] = v;
        }
        for (int i = tid; i < 64*8*7; i += 256) {
            int co = i / 56, rem = i - co*56;
            int ci = rem / 7, kw = rem - ci*7;
            float v = w[((size_t)(co0+co)*CP + cc+ci)*7 + kw];
            s_wp[co][ci][kw] = pack2(v, v);
        }
        __syncthreads();
        #pragma unroll
        for (int ci = 0; ci < 8; ci++) {
            float2 f2[7];
            #pragma unroll
            for (int t = 0; t < 7; t++) f2[t] = *(const float2*)&s_in[ci][y][xq + 2*t];
            const float* f = (const float*)f2;
            #pragma unroll
            for (int kw = 0; kw < 7; kw++) {
                ull iv[4];
                #pragma unroll
                for (int p = 0; p < 4; p++) iv[p] = pack2(f[2*p + kw], f[2*p + kw + 1]);
                #pragma unroll
                for (int j = 0; j < 8; j++) {
                    ull wv2 = s_wp[cg*8 + j][ci][kw];
                    #pragma unroll
                    for (int p = 0; p < 4; p++) ffma2(acc[j][p], wv2, iv[p]);
                }
            }
        }
        __syncthreads();
    }
    #pragma unroll
    for (int j = 0; j < 8; j++) {
        int co = co0 + cg*8 + j;
        #pragma unroll
        for (int p = 0; p < 4; p++) {
            float v0, v1; unpack2(acc[j][p], v0, v1);
            *(float2*)&out[(((size_t)b*CP + co)*HH + y0+y)*WW + xq + 2*p] = make_float2(v0, v1);
        }
    }
}

// ---------------- 7x1 conv (KH=7, pad 3), packed weights, fused stats --------
// 256 threads; block = 64co x 8y x 32x; thread = 8co x 4y x 2x
__global__ void __launch_bounds__(256) conv7x1_kernel(const float* __restrict__ in,
                                                      float* __restrict__ out,
                                                      const float* __restrict__ w,
                                                      int oslot) {
    __shared__ __align__(16) float s_in[8][14][32];   // 14.3 KB
    __shared__ ull s_wp[64][8][7];                    // 28.7 KB
    int tid = threadIdx.x;
    int co0 = blockIdx.x * 64, y0 = blockIdx.y * 8, b = blockIdx.z;
    int xp = tid & 15, yh = (tid >> 4) & 1, cg = tid >> 5;
    ull acc[8][4];
    #pragma unroll
    for (int j = 0; j < 8; j++)
        #pragma unroll
        for (int k = 0; k < 4; k++) acc[j][k] = 0ull;

    for (int cc = 0; cc < CP; cc += 8) {
        for (int i = tid; i < 8*14*32; i += 256) {
            int ci = i / 448, rem = i - ci*448;
            int r = rem >> 5, q = rem & 31;
            int yy = y0 + r - 3;
            float v = 0.f;
            if (yy >= 0 && yy < HH) v = in[(((size_t)b*CP + cc+ci)*HH + yy)*WW + q];
            s_in[ci][r][q] = v;
        }
        for (int i = tid; i < 64*8*7; i += 256) {
            int co = i / 56, rem = i - co*56;
            int ci = rem / 7, kh = rem - ci*7;
            float v = w[((size_t)(co0+co)*CP + cc+ci)*7 + kh];
            s_wp[co][ci][kh] = pack2(v, v);
        }
        __syncthreads();
        #pragma unroll
        for (int ci = 0; ci < 8; ci++) {
            ull iv[10];
            #pragma unroll
            for (int r = 0; r < 10; r++) iv[r] = *(const ull*)&s_in[ci][yh*4 + r][2*xp];
            #pragma unroll
            for (int kh = 0; kh < 7; kh++) {
                #pragma unroll
                for (int j = 0; j < 8; j++) {
                    ull wv2 = s_wp[cg*8 + j][ci][kh];
                    #pragma unroll
                    for (int k = 0; k < 4; k++) ffma2(acc[j][k], wv2, iv[k + kh]);
                }
            }
        }
        __syncthreads();
    }
    #pragma unroll
    for (int j = 0; j < 8; j++) {
        int co = co0 + cg*8 + j;
        float s = 0.f, s2 = 0.f;
        #pragma unroll
        for (int k = 0; k < 4; k++) {
            float v0, v1; unpack2(acc[j][k], v0, v1);
            *(float2*)&out[(((size_t)b*CP + co)*HH + y0 + yh*4 + k)*WW + 2*xp] = make_float2(v0, v1);
            s += v0 + v1; s2 += v0*v0 + v1*v1;
        }
        #pragma unroll
        for (int o = 16; o > 0; o >>= 1) {
            s  += __shfl_xor_sync(0xffffffffu, s,  o);
            s2 += __shfl_xor_sync(0xffffffffu, s2, o);
        }
        if ((tid & 31) == 0 && oslot >= 0) {
            atomicAdd(&g_ssum [oslot*CP + co], (double)s);
            atomicAdd(&g_ssum2[oslot*CP + co], (double)s2);
        }
    }
}

// ---------------- final combine + scatter (float4) ----------------------------
__global__ void combine_kernel(const float* __restrict__ wv, float* __restrict__ out) {
    int n4 = blockIdx.x * 256 + threadIdx.x;   // < NSEL/4
    int n = n4 << 2;
    int b = n >> 17, p = (n >> 10) & 127, hw = n & 1023;
    float m0 = g_meanv[0*CP+p],  r0 = g_rstdv[0*CP+p];
    float m1 = g_meanv[1*CP+p],  r1 = g_rstdv[1*CP+p];
    float m3 = g_meanv[3*CP+p],  r3 = g_rstdv[3*CP+p];
    float m5 = g_meanv[5*CP+p],  r5 = g_rstdv[5*CP+p];
    float m7 = g_meanv[7*CP+p],  r7 = g_rstdv[7*CP+p];
    float m8 = g_meanv[8*CP+p],  r8 = g_rstdv[8*CP+p];
    float m9 = g_meanv[9*CP+p],  r9 = g_rstdv[9*CP+p];
    float mA = g_meanv[10*CP+p], rA = g_rstdv[10*CP+p];
    float w1=wv[1],w2=wv[2],w3=wv[3],w4=wv[4],w5=wv[5],w6=wv[6],w7=wv[7],w8=wv[8],w9=wv[9];
    float a[4] = {0.f,0.f,0.f,0.f};
    { float4 v = *(const float4*)&g_bmax[n];  const float* q=(const float*)&v;
      #pragma unroll
      for (int t=0;t<4;t++) a[t] += w1*(q[t]-m0)*r0; }
    { float4 v = *(const float4*)&g_bavg[n];  const float* q=(const float*)&v;
      #pragma unroll
      for (int t=0;t<4;t++) a[t] += w2*(q[t]-m1)*r1; }
    { float4 v = *(const float4*)&g_xtemp[n]; const float* q=(const float*)&v;
      #pragma unroll
      for (int t=0;t<4;t++) a[t] += w3*q[t]; }
    { float4 v = *(const float4*)&g_s3[n];    const float* q=(const float*)&v;
      #pragma unroll
      for (int t=0;t<4;t++) a[t] += w4*(q[t]-m3)*r3; }
    { float4 v = *(const float4*)&g_s5[n];    const float* q=(const float*)&v;
      #pragma unroll
      for (int t=0;t<4;t++) a[t] += w5*(q[t]-m5)*r5; }
    { float4 v = *(const float4*)&g_s7[n];    const float* q=(const float*)&v;
      #pragma unroll
      for (int t=0;t<4;t++) a[t] += w6*(q[t]-m7)*r7; }
    { float4 v = *(const float4*)&g_d3[n];    const float* q=(const float*)&v;
      #pragma unroll
      for (int t=0;t<4;t++) a[t] += w7*(q[t]-m8)*r8; }
    { float4 v = *(const float4*)&g_d5[n];    const float* q=(const float*)&v;
      #pragma unroll
      for (int t=0;t<4;t++) a[t] += w8*(q[t]-m9)*r9; }
    { float4 v = *(const float4*)&g_c7[n];    const float* q=(const float*)&v;
      #pragma unroll
      for (int t=0;t<4;t++) a[t] += w9*(q[t]-mA)*rA; }
    int cs = g_idx[p];
    *(float4*)&out[(((size_t)b*C + cs) << 10) + hw] = make_float4(a[0],a[1],a[2],a[3]);
}

// =============================================================================
extern "C" void kernel_launch(void* const* d_in, const int* in_sizes, int n_in,
                              void* d_out, int out_size) {
    const float* x        = (const float*)d_in[0];
    const float* weights  = (const float*)d_in[1];
    const float* wall     = (const float*)d_in[2];
    const float* w_fc1    = (const float*)d_in[3];
    const float* w_fc2    = (const float*)d_in[4];
    const float* sep3_dw1 = (const float*)d_in[5];
    const float* sep3_pw1 = (const float*)d_in[6];
    const float* sep3_dw2 = (const float*)d_in[7];
    const float* sep3_pw2 = (const float*)d_in[8];
    const float* sep5_dw1 = (const float*)d_in[9];
    const float* sep5_pw1 = (const float*)d_in[10];
    const float* sep5_dw2 = (const float*)d_in[11];
    const float* sep5_pw2 = (const float*)d_in[12];
    const float* sep7_dw1 = (const float*)d_in[13];
    const float* sep7_pw1 = (const float*)d_in[14];
    const float* sep7_dw2 = (const float*)d_in[15];
    const float* sep7_pw2 = (const float*)d_in[16];
    const float* dil3_dw  = (const float*)d_in[17];
    const float* dil3_pw  = (const float*)d_in[18];
    const float* dil5_dw  = (const float*)d_in[19];
    const float* dil5_pw  = (const float*)d_in[20];
    const float* w_1x7    = (const float*)d_in[21];
    const float* w_7x1    = (const float*)d_in[22];
    float* out = (float*)d_out;

    // Resolve REAL device addresses (host shadow symbols are ATS garbage on GB300).
    float *t_xtemp,*t_1,*t_2,*t_bmax,*t_bavg,*t_s3,*t_s5,*t_s7,*t_d3,*t_d5,*t_c7;
    { void* p;
      cudaGetSymbolAddress(&p, g_xtemp); t_xtemp=(float*)p;
      cudaGetSymbolAddress(&p, g_t1);    t_1    =(float*)p;
      cudaGetSymbolAddress(&p, g_t2);    t_2    =(float*)p;
      cudaGetSymbolAddress(&p, g_bmax);  t_bmax =(float*)p;
      cudaGetSymbolAddress(&p, g_bavg);  t_bavg =(float*)p;
      cudaGetSymbolAddress(&p, g_s3);    t_s3   =(float*)p;
      cudaGetSymbolAddress(&p, g_s5);    t_s5   =(float*)p;
      cudaGetSymbolAddress(&p, g_s7);    t_s7   =(float*)p;
      cudaGetSymbolAddress(&p, g_d3);    t_d3   =(float*)p;
      cudaGetSymbolAddress(&p, g_d5);    t_d5   =(float*)p;
      cudaGetSymbolAddress(&p, g_c7);    t_c7   =(float*)p; }

    const int GSEL4 = NSEL / 1024;   // 8192
    const int GALL4 = NALL / 1024;   // 32768
    dim3 gcv(2, 4, B);               // 64co x 8y tiles (pw + 7-convs)
    const int GDW = B * CP;          // 8192

    // 0-2: dependency prefix for conv1x7
    attn_fused_kernel<<<B, 512>>>(x, w_fc1, wall, w_fc2);
    slist_topk_kernel<<<1, C>>>();
    gather4_kernel<<<GSEL4, 256>>>(x);

    // 3: conv1x7 (ncu samples launch index 3)
    conv1x7_kernel<<<gcv, 256>>>(t_xtemp, t_1, w_1x7);
    conv7x1_kernel<<<gcv, 256>>>(t_1, t_c7, w_7x1, 10);

    // independent passes
    scale4_kernel<<<GALL4, 256>>>(x, out);
    pool3f_kernel<<<GDW, 256>>>(t_xtemp, t_bmax, t_bavg);

    // sep convs: slots mid/fin = (2,3) (4,5) (6,7)
    dw_conv_kernel<3,1,1><<<GDW, 256>>>(t_xtemp, t_1, sep3_dw1, 0);
    pw_conv_kernel<<<gcv, 256>>>(t_1, t_2, sep3_pw1, 2);
    dw_conv_kernel<3,1,2><<<GDW, 256>>>(t_2, t_1, sep3_dw2, 2);
    pw_conv_kernel<<<gcv, 256>>>(t_1, t_s3, sep3_pw2, 3);

    dw_conv_kernel<5,1,1><<<GDW, 256>>>(t_xtemp, t_1, sep5_dw1, 0);
    pw_conv_kernel<<<gcv, 256>>>(t_1, t_2, sep5_pw1, 4);
    dw_conv_kernel<5,1,2><<<GDW, 256>>>(t_2, t_1, sep5_dw2, 4);
    pw_conv_kernel<<<gcv, 256>>>(t_1, t_s5, sep5_pw2, 5);

    dw_conv_kernel<7,1,1><<<GDW, 256>>>(t_xtemp, t_1, sep7_dw1, 0);
    pw_conv_kernel<<<gcv, 256>>>(t_1, t_2, sep7_pw1, 6);
    dw_conv_kernel<7,1,2><<<GDW, 256>>>(t_2, t_1, sep7_dw2, 6);
    pw_conv_kernel<<<gcv, 256>>>(t_1, t_s7, sep7_pw2, 7);

    // dilated convs
    dw_conv_kernel<3,2,1><<<GDW, 256>>>(t_xtemp, t_1, dil3_dw, 0);
    pw_conv_kernel<<<gcv, 256>>>(t_1, t_d3, dil3_pw, 8);
    dw_conv_kernel<5,2,1><<<GDW, 256>>>(t_xtemp, t_1, dil5_dw, 0);
    pw_conv_kernel<<<gcv, 256>>>(t_1, t_d5, dil5_pw, 9);

    // finalize all stats, combine, scatter
    finalize_kernel<<<NSLOT, 128>>>();
    combine_kernel<<<GSEL4, 256>>>(weights, out);
}

// round 11
// speedup vs baseline: 1.1308x; 1.1308x over previous
#include <cuda_runtime.h>
#include <cuda_bf16.h>
#include <math.h>

#define B   64
#define C   512
#define CP  128
#define HH  32
#define WW  32
#define HW  1024
#define NSEL (B*CP*HW)       // 8388608
#define NALL (B*C*HW)        // 33554432
#define NSLOT 11

// ---------------- scratch (device globals; no allocs allowed) ----------------
__device__ float g_ca[B*C];
__device__ int   g_idx[CP];
__device__ float g_xtemp[NSEL];
__device__ float g_t1[NSEL];
__device__ float g_t2[NSEL];
__device__ float g_bmax[NSEL];
__device__ float g_bavg[NSEL];
__device__ float g_s3[NSEL];
__device__ float g_s5[NSEL];
__device__ float g_s7[NSEL];
__device__ float g_d3[NSEL];
__device__ float g_d5[NSEL];
__device__ float g_c7[NSEL];
__device__ double g_ssum [NSLOT*CP];
__device__ double g_ssum2[NSLOT*CP];
__device__ float  g_meanv[NSLOT*CP];
__device__ float  g_rstdv[NSLOT*CP];

// slots: 0 max, 1 avg, 2 sep3mid, 3 sep3fin, 4 sep5mid, 5 sep5fin,
//        6 sep7mid, 7 sep7fin, 8 dil3, 9 dil5, 10 c7

typedef unsigned long long ull;
__device__ __forceinline__ ull pack2(float a, float b){
    ull r; asm("mov.b64 %0,{%1,%2};":"=l"(r):"f"(a),"f"(b)); return r;
}
__device__ __forceinline__ void unpack2(ull v, float&a, float&b){
    asm("mov.b64 {%0,%1},%2;":"=f"(a),"=f"(b):"l"(v));
}
__device__ __forceinline__ void ffma2(ull&d, ull a, ull b){
    asm("fma.rn.f32x2 %0,%1,%2,%0;":"+l"(d):"l"(a),"l"(b));
}

// ---------------- 0. fused global pooling + attention MLP (+ stats zero) -----
__global__ void __launch_bounds__(512) attn_fused_kernel(
        const float* __restrict__ x, const float* __restrict__ fc1,
        const float* __restrict__ wa, const float* __restrict__ fc2) {
    int b = blockIdx.x, tid = threadIdx.x;     // 512 threads
    __shared__ float pooled[1024];             // [avg 512 | max 512]
    __shared__ float red[16];
    __shared__ float s_y[10], s_A[100], s_y2[10];
    if (b == 0) {
        for (int i = tid; i < NSLOT*CP; i += 512) { g_ssum[i] = 0.0; g_ssum2[i] = 0.0; }
    }
    int w = tid >> 5, l = tid & 31;
    for (int j = 0; j < 32; j++) {
        int c = w*32 + j;
        const float* p = x + ((size_t)(b*C + c) << 10);
        float s = 0.f, m = -INFINITY;
        #pragma unroll 4
        for (int k = 0; k < 32; k++) { float v = p[l + 32*k]; s += v; m = fmaxf(m, v); }
        #pragma unroll
        for (int o = 16; o > 0; o >>= 1) {
            s += __shfl_xor_sync(0xffffffffu, s, o);
            m = fmaxf(m, __shfl_xor_sync(0xffffffffu, m, o));
        }
        if (l == 0) { pooled[c] = s * (1.f/1024.f); pooled[C + c] = m; }
    }
    __syncthreads();
    for (int j = 0; j < 10; j++) {
        float local = pooled[tid] * fc1[j*2*C + tid] + pooled[512 + tid] * fc1[j*2*C + 512 + tid];
        #pragma unroll
        for (int o = 16; o > 0; o >>= 1) local += __shfl_xor_sync(0xffffffffu, local, o);
        if (l == 0) red[w] = local;
        __syncthreads();
        if (tid == 0) { float t = 0.f; for (int q = 0; q < 16; q++) t += red[q]; s_y[j] = t; }
        __syncthreads();
    }
    if (tid < 100) {
        int j = tid / 10, k = tid % 10;
        float a = 0.f;
        for (int m = 0; m < 14; m++) a += wa[m*10 + j] * wa[m*10 + k];
        s_A[tid] = a;
    }
    __syncthreads();
    if (tid < 10) {
        float v = 0.f;
        for (int k = 0; k < 10; k++) v += s_y[k] * s_A[tid*10 + k];
        s_y2[tid] = fmaxf(v, 0.f);
    }
    __syncthreads();
    {
        int c = tid;
        float v = 0.f;
        for (int j = 0; j < 10; j++) v += s_y2[j] * fc2[c*10 + j];
        g_ca[b*C + c] = 1.f / (1.f + expf(-v));
    }
}

// ---------------- 1. slist + exact lax.top_k ordering (merged) ----------------
__global__ void slist_topk_kernel() {
    __shared__ float v[C];
    int c = threadIdx.x;                       // 512
    float s = 0.f;
    for (int b = 0; b < B; b++) s += g_ca[b*C + c];
    v[c] = s; __syncthreads();
    float mv = v[c];
    int rank = 0;
    for (int i = 0; i < C; i++) {
        float o = v[i];
        rank += (o > mv) || (o == mv && i < c);
    }
    if (rank < CP) g_idx[rank] = c;
}

// ---------------- 2. gather xtemp = (x*ca)[:, idx] (float4) ----------------
__global__ void gather4_kernel(const float* __restrict__ x) {
    int n4 = blockIdx.x * 256 + threadIdx.x;   // < NSEL/4
    int n = n4 << 2;
    int b = n >> 17, p = (n >> 10) & 127, hw = n & 1023;
    int cs = g_idx[p];
    float ca = g_ca[b*C + cs];
    float4 v = *(const float4*)&x[(((size_t)b*C + cs) << 10) + hw];
    v.x *= ca; v.y *= ca; v.z *= ca; v.w *= ca;
    *(float4*)&g_xtemp[n] = v;
}

// ---------------- scale x by ca into d_out (float4) ----------------
__global__ void scale4_kernel(const float* __restrict__ x, float* __restrict__ out) {
    int n4 = blockIdx.x * 256 + threadIdx.x;   // < NALL/4
    int n = n4 << 2;
    float ca = g_ca[n >> 10];
    float4 v = *(const float4*)&x[n];
    v.x *= ca; v.y *= ca; v.z *= ca; v.w *= ca;
    *(float4*)&out[n] = v;
}

// ---------------- fused 3x3 max+avg pool + stats (smem tile) ----------------
__global__ void __launch_bounds__(256) pool3f_kernel(const float* __restrict__ in,
                                                     float* __restrict__ omax,
                                                     float* __restrict__ oavg) {
    __shared__ float s[34][35];
    __shared__ float rsm[8][4];
    int bc = blockIdx.x;
    int tid = threadIdx.x;
    const float* ip = in + ((size_t)bc << 10);
    for (int i = tid; i < 34*34; i += 256) {
        int r = i / 34, q = i - r*34;
        int y = r - 1, x = q - 1;
        s[r][q] = (y >= 0 && y < 32 && x >= 0 && x < 32) ? ip[y*32 + x] : 0.f;
    }
    __syncthreads();
    int y = tid >> 3, x0 = (tid & 7) * 4;
    float vmax[4], vavg[4];
    int yl = (y > 0 ? y-1 : 0), yhh = (y < 31 ? y+1 : 31);
    int ch = yhh - yl + 1;
    #pragma unroll
    for (int t = 0; t < 4; t++) {
        int x = x0 + t;
        float m = -INFINITY, sm = 0.f;
        #pragma unroll
        for (int dy = 0; dy < 3; dy++) {
            int yy = y + dy;
            bool yok = (yy >= 1 && yy <= 32);
            #pragma unroll
            for (int dx = 0; dx < 3; dx++) {
                int xx = x + dx;
                float v = s[yy][xx];
                sm += v;
                if (yok && xx >= 1 && xx <= 32) m = fmaxf(m, v);
            }
        }
        int xl = (x > 0 ? x-1 : 0), xh = (x < 31 ? x+1 : 31);
        int cnt = ch * (xh - xl + 1);
        vmax[t] = m; vavg[t] = sm / (float)cnt;
    }
    size_t base = ((size_t)bc << 10) + y*32 + x0;
    *(float4*)&omax[base] = make_float4(vmax[0],vmax[1],vmax[2],vmax[3]);
    *(float4*)&oavg[base] = make_float4(vavg[0],vavg[1],vavg[2],vavg[3]);
    float sM=0,sM2=0,sA=0,sA2=0;
    #pragma unroll
    for (int t = 0; t < 4; t++) { sM += vmax[t]; sM2 += vmax[t]*vmax[t]; sA += vavg[t]; sA2 += vavg[t]*vavg[t]; }
    #pragma unroll
    for (int o = 16; o > 0; o >>= 1) {
        sM  += __shfl_xor_sync(0xffffffffu, sM,  o);
        sM2 += __shfl_xor_sync(0xffffffffu, sM2, o);
        sA  += __shfl_xor_sync(0xffffffffu, sA,  o);
        sA2 += __shfl_xor_sync(0xffffffffu, sA2, o);
    }
    int w = tid >> 5;
    if ((tid & 31) == 0) { rsm[w][0]=sM; rsm[w][1]=sM2; rsm[w][2]=sA; rsm[w][3]=sA2; }
    __syncthreads();
    if (tid == 0) {
        float a=0,b2=0,c2=0,d2=0;
        for (int q = 0; q < 8; q++) { a+=rsm[q][0]; b2+=rsm[q][1]; c2+=rsm[q][2]; d2+=rsm[q][3]; }
        int c = bc & 127;
        atomicAdd(&g_ssum [0*CP + c], (double)a);
        atomicAdd(&g_ssum2[0*CP + c], (double)b2);
        atomicAdd(&g_ssum [1*CP + c], (double)c2);
        atomicAdd(&g_ssum2[1*CP + c], (double)d2);
    }
}

// ---------------- finalize stats ----------------
__global__ void finalize_kernel() {
    int s = blockIdx.x, c = threadIdx.x;       // 11 x 128
    double su = g_ssum[s*CP+c], sq = g_ssum2[s*CP+c];
    double m  = su * (1.0/65536.0);
    double var = sq * (1.0/65536.0) - m*m;
    g_meanv[s*CP+c] = (float)m;
    g_rstdv[s*CP+c] = (float)rsqrt(var + 1e-5);
}

// ---------------- depthwise conv, smem tile; TRANS: 1 relu, 2 bn+relu --------
template<int K, int DIL, int TRANS>
__global__ void __launch_bounds__(256) dw_conv_kernel(const float* __restrict__ in,
                                                      float* __restrict__ out,
                                                      const float* __restrict__ w,
                                                      int islot) {
    constexpr int P  = (DIL==1) ? (K/2) : (K-1);
    constexpr int SW = 32 + 2*P;
    constexpr int SWP = SW + 1;
    constexpr int SPAN = 4 + (K-1)*DIL;
    __shared__ float s[SW][SWP];
    __shared__ float s_mr[2];
    int bc = blockIdx.x;
    int c = bc & 127;
    int tid = threadIdx.x;
    if (TRANS == 2 && tid == 0) {
        double su = g_ssum[islot*CP + c], sq = g_ssum2[islot*CP + c];
        double m = su * (1.0/65536.0);
        double var = sq * (1.0/65536.0) - m*m;
        s_mr[0] = (float)m; s_mr[1] = (float)rsqrt(var + 1e-5);
    }
    if (TRANS == 2) __syncthreads();
    float mean = 0.f, rstd = 1.f;
    if (TRANS == 2) { mean = s_mr[0]; rstd = s_mr[1]; }
    const float* ip = in + ((size_t)bc << 10);
    for (int i = tid; i < SW*SW; i += 256) {
        int r = i / SW, q = i - r*SW;
        int y = r - P, x = q - P;
        float v = 0.f;
        if (y >= 0 && y < 32 && x >= 0 && x < 32) {
            v = ip[y*32 + x];
            if (TRANS == 1) v = fmaxf(v, 0.f);
            else if (TRANS == 2) v = fmaxf((v - mean)*rstd, 0.f);
        }
        s[r][q] = v;
    }
    float wr[K][K];
    #pragma unroll
    for (int i = 0; i < K; i++)
        #pragma unroll
        for (int j = 0; j < K; j++) wr[i][j] = w[(c*K + i)*K + j];
    __syncthreads();
    int y = tid >> 3, x0 = (tid & 7) * 4;
    float acc[4] = {0.f, 0.f, 0.f, 0.f};
    #pragma unroll
    for (int i = 0; i < K; i++) {
        float r[SPAN];
        #pragma unroll
        for (int q = 0; q < SPAN; q++) r[q] = s[y + i*DIL][x0 + q];
        #pragma unroll
        for (int j = 0; j < K; j++)
            #pragma unroll
            for (int t = 0; t < 4; t++) acc[t] = fmaf(wr[i][j], r[j*DIL + t], acc[t]);
    }
    *(float4*)&out[((size_t)bc << 10) + y*32 + x0] = make_float4(acc[0],acc[1],acc[2],acc[3]);
}

// ---------------- pointwise conv 128->128, f32x2, packed weights -------------
// 256 threads; block = 64co x 8y x 32x; thread = 8co x 4y x 2x; warp = co-group
__global__ void __launch_bounds__(256) pw_conv_kernel(const float* __restrict__ in,
                                                      float* __restrict__ out,
                                                      const float* __restrict__ w,
                                                      int oslot) {
    __shared__ __align__(16) float s_in[16][8][32];   // 16 KB
    __shared__ ull s_wp[64][16];                      // (w,w) pairs, 8 KB
    int tid = threadIdx.x;
    int co0 = blockIdx.x * 64, y0 = blockIdx.y * 8, b = blockIdx.z;
    int xp = tid & 15, yh = (tid >> 4) & 1, cg = tid >> 5;
    ull acc[8][4];
    #pragma unroll
    for (int j = 0; j < 8; j++)
        #pragma unroll
        for (int k = 0; k < 4; k++) acc[j][k] = 0ull;

    for (int cc = 0; cc < CP; cc += 16) {
        { int co = tid >> 2, cq = (tid & 3) * 4;
          float4 v = *(const float4*)&w[(size_t)(co0+co)*CP + cc + cq];
          s_wp[co][cq+0] = pack2(v.x, v.x);
          s_wp[co][cq+1] = pack2(v.y, v.y);
          s_wp[co][cq+2] = pack2(v.z, v.z);
          s_wp[co][cq+3] = pack2(v.w, v.w); }
        #pragma unroll
        for (int i = tid; i < 1024; i += 256) {       // float4 units
            int ci = i >> 6, rem = i & 63;
            int y = rem >> 3, h = rem & 7;
            *(float4*)&s_in[ci][y][h*4] =
                *(const float4*)&in[(((size_t)b*CP + cc+ci)*HH + y0+y)*WW + h*4];
        }
        __syncthreads();
        #pragma unroll
        for (int ci = 0; ci < 16; ci++) {
            ull iv[4];
            #pragma unroll
            for (int k = 0; k < 4; k++) iv[k] = *(const ull*)&s_in[ci][yh*4 + k][2*xp];
            #pragma unroll
            for (int j = 0; j < 8; j++) {
                ull wv2 = s_wp[cg*8 + j][ci];
                #pragma unroll
                for (int k = 0; k < 4; k++) ffma2(acc[j][k], wv2, iv[k]);
            }
        }
        __syncthreads();
    }
    #pragma unroll
    for (int j = 0; j < 8; j++) {
        int co = co0 + cg*8 + j;
        float s = 0.f, s2 = 0.f;
        #pragma unroll
        for (int k = 0; k < 4; k++) {
            float v0, v1; unpack2(acc[j][k], v0, v1);
            *(float2*)&out[(((size_t)b*CP + co)*HH + y0 + yh*4 + k)*WW + 2*xp] = make_float2(v0, v1);
            s += v0 + v1; s2 += v0*v0 + v1*v1;
        }
        #pragma unroll
        for (int o = 16; o > 0; o >>= 1) {
            s  += __shfl_xor_sync(0xffffffffu, s,  o);
            s2 += __shfl_xor_sync(0xffffffffu, s2, o);
        }
        if ((tid & 31) == 0 && oslot >= 0) {
            atomicAdd(&g_ssum [oslot*CP + co], (double)s);
            atomicAdd(&g_ssum2[oslot*CP + co], (double)s2);
        }
    }
}

// ---------------- 1x7 conv (KW=7, pad 3), relu-in, dual-shifted copies -------
// Dynamic smem: s0[16][8][40], s1 (shifted left 1), s_wp[64][16][7] = 96 KB.
// 256 threads; block = 64co x 8y x 32x; thread = 8co x 4y(half) x 2x.
// Every input pair is an ALIGNED LDS.64: even kw from s0, odd kw from s1.
__global__ void __launch_bounds__(256) conv1x7_kernel(const float* __restrict__ in,
                                                      float* __restrict__ out,
                                                      const float* __restrict__ w) {
    extern __shared__ __align__(16) char dsm[];
    float* s0  = (float*)dsm;                  // 16*8*40 floats
    float* s1  = s0 + 16*8*40;                 // shifted copy
    ull*   swp = (ull*)(s1 + 16*8*40);         // [64][16][7]
    int tid = threadIdx.x;
    int co0 = blockIdx.x * 64, y0 = blockIdx.y * 8, b = blockIdx.z;
    int xp = tid & 15, yh = (tid >> 4) & 1, cg = tid >> 5;
    ull acc[8][4];
    #pragma unroll
    for (int j = 0; j < 8; j++)
        #pragma unroll
        for (int k = 0; k < 4; k++) acc[j][k] = 0ull;

    for (int cc = 0; cc < CP; cc += 16) {
        for (int i = tid; i < 16*8*40; i += 256) {
            int ci = i / 320, rem = i - ci*320;
            int yy = rem / 40, q = rem - yy*40;
            int x = q - 3;
            float v = 0.f;
            if (x >= 0 && x < WW)
                v = fmaxf(in[(((size_t)b*CP + cc+ci)*HH + y0+yy)*WW + x], 0.f);
            int o = (ci*8 + yy)*40 + q;
            s0[o] = v;
            if (q > 0) s1[o - 1] = v;
        }
        for (int i = tid; i < 64*16*7; i += 256) {
            int co = i / 112, rem = i - co*112;
            int ci = rem / 7, kw = rem - ci*7;
            float v = w[((size_t)(co0+co)*CP + cc+ci)*7 + kw];
            swp[(co*16 + ci)*7 + kw] = pack2(v, v);
        }
        __syncthreads();
        #pragma unroll
        for (int ci = 0; ci < 16; ci++) {
            int rb = (ci*8 + yh*4)*40;
            #pragma unroll
            for (int kw = 0; kw < 7; kw++) {
                const float* src = (kw & 1) ? s1 : s0;
                int qq = 2*xp + kw - (kw & 1);       // even -> aligned LDS.64
                ull iv[4];
                #pragma unroll
                for (int k = 0; k < 4; k++) iv[k] = *(const ull*)&src[rb + k*40 + qq];
                #pragma unroll
                for (int j = 0; j < 8; j++) {
                    ull wv2 = swp[((cg*8 + j)*16 + ci)*7 + kw];
                    #pragma unroll
                    for (int k = 0; k < 4; k++) ffma2(acc[j][k], wv2, iv[k]);
                }
            }
        }
        __syncthreads();
    }
    #pragma unroll
    for (int j = 0; j < 8; j++) {
        int co = co0 + cg*8 + j;
        #pragma unroll
        for (int k = 0; k < 4; k++) {
            float v0, v1; unpack2(acc[j][k], v0, v1);
            *(float2*)&out[(((size_t)b*CP + co)*HH + y0 + yh*4 + k)*WW + 2*xp] = make_float2(v0, v1);
        }
    }
}

// ---------------- 7x1 conv (KH=7, pad 3), packed weights, ci=16, stats -------
// Dynamic smem: s_in[16][14][32] + s_wp[64][16][7] = 84 KB.
// 256 threads; block = 64co x 8y x 32x; thread = 8co x 4y(half) x 2x.
__global__ void __launch_bounds__(256) conv7x1_kernel(const float* __restrict__ in,
                                                      float* __restrict__ out,
                                                      const float* __restrict__ w,
                                                      int oslot) {
    extern __shared__ __align__(16) char dsm[];
    float* sin = (float*)dsm;                  // 16*14*32 floats
    ull*   swp = (ull*)(sin + 16*14*32);       // [64][16][7]
    int tid = threadIdx.x;
    int co0 = blockIdx.x * 64, y0 = blockIdx.y * 8, b = blockIdx.z;
    int xp = tid & 15, yh = (tid >> 4) & 1, cg = tid >> 5;
    ull acc[8][4];
    #pragma unroll
    for (int j = 0; j < 8; j++)
        #pragma unroll
        for (int k = 0; k < 4; k++) acc[j][k] = 0ull;

    for (int cc = 0; cc < CP; cc += 16) {
        for (int i = tid; i < 16*14*32; i += 256) {
            int ci = i / 448, rem = i - ci*448;
            int r = rem >> 5, q = rem & 31;
            int yy = y0 + r - 3;
            float v = 0.f;
            if (yy >= 0 && yy < HH) v = in[(((size_t)b*CP + cc+ci)*HH + yy)*WW + q];
            sin[(ci*14 + r)*32 + q] = v;
        }
        for (int i = tid; i < 64*16*7; i += 256) {
            int co = i / 112, rem = i - co*112;
            int ci = rem / 7, kh = rem - ci*7;
            float v = w[((size_t)(co0+co)*CP + cc+ci)*7 + kh];
            swp[(co*16 + ci)*7 + kh] = pack2(v, v);
        }
        __syncthreads();
        #pragma unroll
        for (int ci = 0; ci < 16; ci++) {
            ull iv[10];
            #pragma unroll
            for (int r = 0; r < 10; r++)
                iv[r] = *(const ull*)&sin[(ci*14 + yh*4 + r)*32 + 2*xp];
            #pragma unroll
            for (int kh = 0; kh < 7; kh++) {
                #pragma unroll
                for (int j = 0; j < 8; j++) {
                    ull wv2 = swp[((cg*8 + j)*16 + ci)*7 + kh];
                    #pragma unroll
                    for (int k = 0; k < 4; k++) ffma2(acc[j][k], wv2, iv[k + kh]);
                }
            }
        }
        __syncthreads();
    }
    #pragma unroll
    for (int j = 0; j < 8; j++) {
        int co = co0 + cg*8 + j;
        float s = 0.f, s2 = 0.f;
        #pragma unroll
        for (int k = 0; k < 4; k++) {
            float v0, v1; unpack2(acc[j][k], v0, v1);
            *(float2*)&out[(((size_t)b*CP + co)*HH + y0 + yh*4 + k)*WW + 2*xp] = make_float2(v0, v1);
            s += v0 + v1; s2 += v0*v0 + v1*v1;
        }
        #pragma unroll
        for (int o = 16; o > 0; o >>= 1) {
            s  += __shfl_xor_sync(0xffffffffu, s,  o);
            s2 += __shfl_xor_sync(0xffffffffu, s2, o);
        }
        if ((tid & 31) == 0 && oslot >= 0) {
            atomicAdd(&g_ssum [oslot*CP + co], (double)s);
            atomicAdd(&g_ssum2[oslot*CP + co], (double)s2);
        }
    }
}

// ---------------- final combine + scatter (float4) ----------------------------
__global__ void combine_kernel(const float* __restrict__ wv, float* __restrict__ out) {
    int n4 = blockIdx.x * 256 + threadIdx.x;   // < NSEL/4
    int n = n4 << 2;
    int b = n >> 17, p = (n >> 10) & 127, hw = n & 1023;
    float m0 = g_meanv[0*CP+p],  r0 = g_rstdv[0*CP+p];
    float m1 = g_meanv[1*CP+p],  r1 = g_rstdv[1*CP+p];
    float m3 = g_meanv[3*CP+p],  r3 = g_rstdv[3*CP+p];
    float m5 = g_meanv[5*CP+p],  r5 = g_rstdv[5*CP+p];
    float m7 = g_meanv[7*CP+p],  r7 = g_rstdv[7*CP+p];
    float m8 = g_meanv[8*CP+p],  r8 = g_rstdv[8*CP+p];
    float m9 = g_meanv[9*CP+p],  r9 = g_rstdv[9*CP+p];
    float mA = g_meanv[10*CP+p], rA = g_rstdv[10*CP+p];
    float w1=wv[1],w2=wv[2],w3=wv[3],w4=wv[4],w5=wv[5],w6=wv[6],w7=wv[7],w8=wv[8],w9=wv[9];
    float a[4] = {0.f,0.f,0.f,0.f};
    { float4 v = *(const float4*)&g_bmax[n];  const float* q=(const float*)&v;
      #pragma unroll
      for (int t=0;t<4;t++) a[t] += w1*(q[t]-m0)*r0; }
    { float4 v = *(const float4*)&g_bavg[n];  const float* q=(const float*)&v;
      #pragma unroll
      for (int t=0;t<4;t++) a[t] += w2*(q[t]-m1)*r1; }
    { float4 v = *(const float4*)&g_xtemp[n]; const float* q=(const float*)&v;
      #pragma unroll
      for (int t=0;t<4;t++) a[t] += w3*q[t]; }
    { float4 v = *(const float4*)&g_s3[n];    const float* q=(const float*)&v;
      #pragma unroll
      for (int t=0;t<4;t++) a[t] += w4*(q[t]-m3)*r3; }
    { float4 v = *(const float4*)&g_s5[n];    const float* q=(const float*)&v;
      #pragma unroll
      for (int t=0;t<4;t++) a[t] += w5*(q[t]-m5)*r5; }
    { float4 v = *(const float4*)&g_s7[n];    const float* q=(const float*)&v;
      #pragma unroll
      for (int t=0;t<4;t++) a[t] += w6*(q[t]-m7)*r7; }
    { float4 v = *(const float4*)&g_d3[n];    const float* q=(const float*)&v;
      #pragma unroll
      for (int t=0;t<4;t++) a[t] += w7*(q[t]-m8)*r8; }
    { float4 v = *(const float4*)&g_d5[n];    const float* q=(const float*)&v;
      #pragma unroll
      for (int t=0;t<4;t++) a[t] += w8*(q[t]-m9)*r9; }
    { float4 v = *(const float4*)&g_c7[n];    const float* q=(const float*)&v;
      #pragma unroll
      for (int t=0;t<4;t++) a[t] += w9*(q[t]-mA)*rA; }
    int cs = g_idx[p];
    *(float4*)&out[(((size_t)b*C + cs) << 10) + hw] = make_float4(a[0],a[1],a[2],a[3]);
}

// =============================================================================
extern "C" void kernel_launch(void* const* d_in, const int* in_sizes, int n_in,
                              void* d_out, int out_size) {
    const float* x        = (const float*)d_in[0];
    const float* weights  = (const float*)d_in[1];
    const float* wall     = (const float*)d_in[2];
    const float* w_fc1    = (const float*)d_in[3];
    const float* w_fc2    = (const float*)d_in[4];
    const float* sep3_dw1 = (const float*)d_in[5];
    const float* sep3_pw1 = (const float*)d_in[6];
    const float* sep3_dw2 = (const float*)d_in[7];
    const float* sep3_pw2 = (const float*)d_in[8];
    const float* sep5_dw1 = (const float*)d_in[9];
    const float* sep5_pw1 = (const float*)d_in[10];
    const float* sep5_dw2 = (const float*)d_in[11];
    const float* sep5_pw2 = (const float*)d_in[12];
    const float* sep7_dw1 = (const float*)d_in[13];
    const float* sep7_pw1 = (const float*)d_in[14];
    const float* sep7_dw2 = (const float*)d_in[15];
    const float* sep7_pw2 = (const float*)d_in[16];
    const float* dil3_dw  = (const float*)d_in[17];
    const float* dil3_pw  = (const float*)d_in[18];
    const float* dil5_dw  = (const float*)d_in[19];
    const float* dil5_pw  = (const float*)d_in[20];
    const float* w_1x7    = (const float*)d_in[21];
    const float* w_7x1    = (const float*)d_in[22];
    float* out = (float*)d_out;

    // Resolve REAL device addresses (host shadow symbols are ATS garbage on GB300).
    float *t_xtemp,*t_1,*t_2,*t_bmax,*t_bavg,*t_s3,*t_s5,*t_s7,*t_d3,*t_d5,*t_c7;
    { void* p;
      cudaGetSymbolAddress(&p, g_xtemp); t_xtemp=(float*)p;
      cudaGetSymbolAddress(&p, g_t1);    t_1    =(float*)p;
      cudaGetSymbolAddress(&p, g_t2);    t_2    =(float*)p;
      cudaGetSymbolAddress(&p, g_bmax);  t_bmax =(float*)p;
      cudaGetSymbolAddress(&p, g_bavg);  t_bavg =(float*)p;
      cudaGetSymbolAddress(&p, g_s3);    t_s3   =(float*)p;
      cudaGetSymbolAddress(&p, g_s5);    t_s5   =(float*)p;
      cudaGetSymbolAddress(&p, g_s7);    t_s7   =(float*)p;
      cudaGetSymbolAddress(&p, g_d3);    t_d3   =(float*)p;
      cudaGetSymbolAddress(&p, g_d5);    t_d5   =(float*)p;
      cudaGetSymbolAddress(&p, g_c7);    t_c7   =(float*)p; }

    // Dynamic smem opt-in for the 7-convs (idempotent; capture-safe: not a stream op)
    const int SM1X7 = (16*8*40*2)*4 + 64*16*7*8;   // 96 KB
    const int SM7X1 = (16*14*32)*4 + 64*16*7*8;    // 84 KB
    cudaFuncSetAttribute(conv1x7_kernel, cudaFuncAttributeMaxDynamicSharedMemorySize, SM1X7);
    cudaFuncSetAttribute(conv7x1_kernel, cudaFuncAttributeMaxDynamicSharedMemorySize, SM7X1);

    const int GSEL4 = NSEL / 1024;   // 8192
    const int GALL4 = NALL / 1024;   // 32768
    dim3 gcv(2, 4, B);               // 64co x 8y tiles (pw + 7-convs)
    const int GDW = B * CP;          // 8192

    // 0-2: dependency prefix for conv1x7
    attn_fused_kernel<<<B, 512>>>(x, w_fc1, wall, w_fc2);
    slist_topk_kernel<<<1, C>>>();
    gather4_kernel<<<GSEL4, 256>>>(x);

    // 3: conv1x7 (ncu samples launch index 3)
    conv1x7_kernel<<<gcv, 256, SM1X7>>>(t_xtemp, t_1, w_1x7);
    conv7x1_kernel<<<gcv, 256, SM7X1>>>(t_1, t_c7, w_7x1, 10);

    // independent passes
    scale4_kernel<<<GALL4, 256>>>(x, out);
    pool3f_kernel<<<GDW, 256>>>(t_xtemp, t_bmax, t_bavg);

    // sep convs: slots mid/fin = (2,3) (4,5) (6,7)
    dw_conv_kernel<3,1,1><<<GDW, 256>>>(t_xtemp, t_1, sep3_dw1, 0);
    pw_conv_kernel<<<gcv, 256>>>(t_1, t_2, sep3_pw1, 2);
    dw_conv_kernel<3,1,2><<<GDW, 256>>>(t_2, t_1, sep3_dw2, 2);
    pw_conv_kernel<<<gcv, 256>>>(t_1, t_s3, sep3_pw2, 3);

    dw_conv_kernel<5,1,1><<<GDW, 256>>>(t_xtemp, t_1, sep5_dw1, 0);
    pw_conv_kernel<<<gcv, 256>>>(t_1, t_2, sep5_pw1, 4);
    dw_conv_kernel<5,1,2><<<GDW, 256>>>(t_2, t_1, sep5_dw2, 4);
    pw_conv_kernel<<<gcv, 256>>>(t_1, t_s5, sep5_pw2, 5);

    dw_conv_kernel<7,1,1><<<GDW, 256>>>(t_xtemp, t_1, sep7_dw1, 0);
    pw_conv_kernel<<<gcv, 256>>>(t_1, t_2, sep7_pw1, 6);
    dw_conv_kernel<7,1,2><<<GDW, 256>>>(t_2, t_1, sep7_dw2, 6);
    pw_conv_kernel<<<gcv, 256>>>(t_1, t_s7, sep7_pw2, 7);

    // dilated convs
    dw_conv_kernel<3,2,1><<<GDW, 256>>>(t_xtemp, t_1, dil3_dw, 0);
    pw_conv_kernel<<<gcv, 256>>>(t_1, t_d3, dil3_pw, 8);
    dw_conv_kernel<5,2,1><<<GDW, 256>>>(t_xtemp, t_1, dil5_dw, 0);
    pw_conv_kernel<<<gcv, 256>>>(t_1, t_d5, dil5_pw, 9);

    // finalize all stats, combine, scatter
    finalize_kernel<<<NSLOT, 128>>>();
    combine_kernel<<<GSEL4, 256>>>(weights, out);
}

// round 14
// speedup vs baseline: 1.2383x; 1.0950x over previous
#include <cuda_runtime.h>
#include <cuda_bf16.h>
#include <math.h>

#define B   64
#define C   512
#define CP  128
#define HH  32
#define WW  32
#define HW  1024
#define NSEL (B*CP*HW)       // 8388608
#define NALL (B*C*HW)        // 33554432
#define NSLOT 11

// ---------------- scratch (device globals; no allocs allowed) ----------------
__device__ float g_ca[B*C];
__device__ int   g_idx[CP];
__device__ float g_xtemp[NSEL];
__device__ float g_t1[NSEL];
__device__ float g_t2[NSEL];
__device__ float g_bmax[NSEL];
__device__ float g_bavg[NSEL];
__device__ float g_s3[NSEL];
__device__ float g_s5[NSEL];
__device__ float g_s7[NSEL];
__device__ float g_d3[NSEL];
__device__ float g_d5[NSEL];
__device__ float g_c7[NSEL];
__device__ double g_ssum [NSLOT*CP];
__device__ double g_ssum2[NSLOT*CP];
__device__ float  g_meanv[NSLOT*CP];
__device__ float  g_rstdv[NSLOT*CP];

// slots: 0 max, 1 avg, 2 sep3mid, 3 sep3fin, 4 sep5mid, 5 sep5fin,
//        6 sep7mid, 7 sep7fin, 8 dil3, 9 dil5, 10 c7

typedef unsigned long long ull;
__device__ __forceinline__ ull pack2(float a, float b){
    ull r; asm("mov.b64 %0,{%1,%2};":"=l"(r):"f"(a),"f"(b)); return r;
}
__device__ __forceinline__ void unpack2(ull v, float&a, float&b){
    asm("mov.b64 {%0,%1},%2;":"=f"(a),"=f"(b):"l"(v));
}
__device__ __forceinline__ void ffma2(ull&d, ull a, ull b){
    asm("fma.rn.f32x2 %0,%1,%2,%0;":"+l"(d):"l"(a),"l"(b));
}

// ---------------- 0. fused global pooling + attention MLP (+ stats zero) -----
__global__ void __launch_bounds__(512) attn_fused_kernel(
        const float* __restrict__ x, const float* __restrict__ fc1,
        const float* __restrict__ wa, const float* __restrict__ fc2) {
    int b = blockIdx.x, tid = threadIdx.x;     // 512 threads
    __shared__ float pooled[1024];             // [avg 512 | max 512]
    __shared__ float red[16];
    __shared__ float s_y[10], s_A[100], s_y2[10];
    if (b == 0) {
        for (int i = tid; i < NSLOT*CP; i += 512) { g_ssum[i] = 0.0; g_ssum2[i] = 0.0; }
    }
    int w = tid >> 5, l = tid & 31;
    for (int j = 0; j < 32; j++) {
        int c = w*32 + j;
        const float* p = x + ((size_t)(b*C + c) << 10);
        float s = 0.f, m = -INFINITY;
        #pragma unroll 4
        for (int k = 0; k < 32; k++) { float v = p[l + 32*k]; s += v; m = fmaxf(m, v); }
        #pragma unroll
        for (int o = 16; o > 0; o >>= 1) {
            s += __shfl_xor_sync(0xffffffffu, s, o);
            m = fmaxf(m, __shfl_xor_sync(0xffffffffu, m, o));
        }
        if (l == 0) { pooled[c] = s * (1.f/1024.f); pooled[C + c] = m; }
    }
    __syncthreads();
    for (int j = 0; j < 10; j++) {
        float local = pooled[tid] * fc1[j*2*C + tid] + pooled[512 + tid] * fc1[j*2*C + 512 + tid];
        #pragma unroll
        for (int o = 16; o > 0; o >>= 1) local += __shfl_xor_sync(0xffffffffu, local, o);
        if (l == 0) red[w] = local;
        __syncthreads();
        if (tid == 0) { float t = 0.f; for (int q = 0; q < 16; q++) t += red[q]; s_y[j] = t; }
        __syncthreads();
    }
    if (tid < 100) {
        int j = tid / 10, k = tid % 10;
        float a = 0.f;
        for (int m = 0; m < 14; m++) a += wa[m*10 + j] * wa[m*10 + k];
        s_A[tid] = a;
    }
    __syncthreads();
    if (tid < 10) {
        float v = 0.f;
        for (int k = 0; k < 10; k++) v += s_y[k] * s_A[tid*10 + k];
        s_y2[tid] = fmaxf(v, 0.f);
    }
    __syncthreads();
    {
        int c = tid;
        float v = 0.f;
        for (int j = 0; j < 10; j++) v += s_y2[j] * fc2[c*10 + j];
        g_ca[b*C + c] = 1.f / (1.f + expf(-v));
    }
}

// ---------------- 1. slist + exact lax.top_k ordering (merged) ----------------
__global__ void slist_topk_kernel() {
    __shared__ float v[C];
    int c = threadIdx.x;                       // 512
    float s = 0.f;
    for (int b = 0; b < B; b++) s += g_ca[b*C + c];
    v[c] = s; __syncthreads();
    float mv = v[c];
    int rank = 0;
    for (int i = 0; i < C; i++) {
        float o = v[i];
        rank += (o > mv) || (o == mv && i < c);
    }
    if (rank < CP) g_idx[rank] = c;
}

// ---------------- 2. gather xtemp = (x*ca)[:, idx] (float4) ----------------
__global__ void gather4_kernel(const float* __restrict__ x) {
    int n4 = blockIdx.x * 256 + threadIdx.x;   // < NSEL/4
    int n = n4 << 2;
    int b = n >> 17, p = (n >> 10) & 127, hw = n & 1023;
    int cs = g_idx[p];
    float ca = g_ca[b*C + cs];
    float4 v = *(const float4*)&x[(((size_t)b*C + cs) << 10) + hw];
    v.x *= ca; v.y *= ca; v.z *= ca; v.w *= ca;
    *(float4*)&g_xtemp[n] = v;
}

// ---------------- scale x by ca into d_out (float4) ----------------
__global__ void scale4_kernel(const float* __restrict__ x, float* __restrict__ out) {
    int n4 = blockIdx.x * 256 + threadIdx.x;   // < NALL/4
    int n = n4 << 2;
    float ca = g_ca[n >> 10];
    float4 v = *(const float4*)&x[n];
    v.x *= ca; v.y *= ca; v.z *= ca; v.w *= ca;
    *(float4*)&out[n] = v;
}

// ---------------- fused 3x3 max+avg pool + stats (smem tile) ----------------
__global__ void __launch_bounds__(256) pool3f_kernel(const float* __restrict__ in,
                                                     float* __restrict__ omax,
                                                     float* __restrict__ oavg) {
    __shared__ float s[34][35];
    __shared__ float rsm[8][4];
    int bc = blockIdx.x;
    int tid = threadIdx.x;
    const float* ip = in + ((size_t)bc << 10);
    for (int i = tid; i < 34*34; i += 256) {
        int r = i / 34, q = i - r*34;
        int y = r - 1, x = q - 1;
        s[r][q] = (y >= 0 && y < 32 && x >= 0 && x < 32) ? ip[y*32 + x] : 0.f;
    }
    __syncthreads();
    int y = tid >> 3, x0 = (tid & 7) * 4;
    float vmax[4], vavg[4];
    int yl = (y > 0 ? y-1 : 0), yhh = (y < 31 ? y+1 : 31);
    int ch = yhh - yl + 1;
    #pragma unroll
    for (int t = 0; t < 4; t++) {
        int x = x0 + t;
        float m = -INFINITY, sm = 0.f;
        #pragma unroll
        for (int dy = 0; dy < 3; dy++) {
            int yy = y + dy;
            bool yok = (yy >= 1 && yy <= 32);
            #pragma unroll
            for (int dx = 0; dx < 3; dx++) {
                int xx = x + dx;
                float v = s[yy][xx];
                sm += v;
                if (yok && xx >= 1 && xx <= 32) m = fmaxf(m, v);
            }
        }
        int xl = (x > 0 ? x-1 : 0), xh = (x < 31 ? x+1 : 31);
        int cnt = ch * (xh - xl + 1);
        vmax[t] = m; vavg[t] = sm / (float)cnt;
    }
    size_t base = ((size_t)bc << 10) + y*32 + x0;
    *(float4*)&omax[base] = make_float4(vmax[0],vmax[1],vmax[2],vmax[3]);
    *(float4*)&oavg[base] = make_float4(vavg[0],vavg[1],vavg[2],vavg[3]);
    float sM=0,sM2=0,sA=0,sA2=0;
    #pragma unroll
    for (int t = 0; t < 4; t++) { sM += vmax[t]; sM2 += vmax[t]*vmax[t]; sA += vavg[t]; sA2 += vavg[t]*vavg[t]; }
    #pragma unroll
    for (int o = 16; o > 0; o >>= 1) {
        sM  += __shfl_xor_sync(0xffffffffu, sM,  o);
        sM2 += __shfl_xor_sync(0xffffffffu, sM2, o);
        sA  += __shfl_xor_sync(0xffffffffu, sA,  o);
        sA2 += __shfl_xor_sync(0xffffffffu, sA2, o);
    }
    int w = tid >> 5;
    if ((tid & 31) == 0) { rsm[w][0]=sM; rsm[w][1]=sM2; rsm[w][2]=sA; rsm[w][3]=sA2; }
    __syncthreads();
    if (tid == 0) {
        float a=0,b2=0,c2=0,d2=0;
        for (int q = 0; q < 8; q++) { a+=rsm[q][0]; b2+=rsm[q][1]; c2+=rsm[q][2]; d2+=rsm[q][3]; }
        int c = bc & 127;
        atomicAdd(&g_ssum [0*CP + c], (double)a);
        atomicAdd(&g_ssum2[0*CP + c], (double)b2);
        atomicAdd(&g_ssum [1*CP + c], (double)c2);
        atomicAdd(&g_ssum2[1*CP + c], (double)d2);
    }
}

// ---------------- finalize stats ----------------
__global__ void finalize_kernel() {
    int s = blockIdx.x, c = threadIdx.x;       // 11 x 128
    double su = g_ssum[s*CP+c], sq = g_ssum2[s*CP+c];
    double m  = su * (1.0/65536.0);
    double var = sq * (1.0/65536.0) - m*m;
    g_meanv[s*CP+c] = (float)m;
    g_rstdv[s*CP+c] = (float)rsqrt(var + 1e-5);
}

// ---------------- depthwise conv, smem tile; TRANS: 1 relu, 2 bn+relu --------
template<int K, int DIL, int TRANS>
__global__ void __launch_bounds__(256) dw_conv_kernel(const float* __restrict__ in,
                                                      float* __restrict__ out,
                                                      const float* __restrict__ w,
                                                      int islot) {
    constexpr int P  = (DIL==1) ? (K/2) : (K-1);
    constexpr int SW = 32 + 2*P;
    constexpr int SWP = SW + 1;
    constexpr int SPAN = 4 + (K-1)*DIL;
    __shared__ float s[SW][SWP];
    __shared__ float s_mr[2];
    int bc = blockIdx.x;
    int c = bc & 127;
    int tid = threadIdx.x;
    if (TRANS == 2 && tid == 0) {
        double su = g_ssum[islot*CP + c], sq = g_ssum2[islot*CP + c];
        double m = su * (1.0/65536.0);
        double var = sq * (1.0/65536.0) - m*m;
        s_mr[0] = (float)m; s_mr[1] = (float)rsqrt(var + 1e-5);
    }
    if (TRANS == 2) __syncthreads();
    float mean = 0.f, rstd = 1.f;
    if (TRANS == 2) { mean = s_mr[0]; rstd = s_mr[1]; }
    const float* ip = in + ((size_t)bc << 10);
    for (int i = tid; i < SW*SW; i += 256) {
        int r = i / SW, q = i - r*SW;
        int y = r - P, x = q - P;
        float v = 0.f;
        if (y >= 0 && y < 32 && x >= 0 && x < 32) {
            v = ip[y*32 + x];
            if (TRANS == 1) v = fmaxf(v, 0.f);
            else if (TRANS == 2) v = fmaxf((v - mean)*rstd, 0.f);
        }
        s[r][q] = v;
    }
    float wr[K][K];
    #pragma unroll
    for (int i = 0; i < K; i++)
        #pragma unroll
        for (int j = 0; j < K; j++) wr[i][j] = w[(c*K + i)*K + j];
    __syncthreads();
    int y = tid >> 3, x0 = (tid & 7) * 4;
    float acc[4] = {0.f, 0.f, 0.f, 0.f};
    #pragma unroll
    for (int i = 0; i < K; i++) {
        float r[SPAN];
        #pragma unroll
        for (int q = 0; q < SPAN; q++) r[q] = s[y + i*DIL][x0 + q];
        #pragma unroll
        for (int j = 0; j < K; j++)
            #pragma unroll
            for (int t = 0; t < 4; t++) acc[t] = fmaf(wr[i][j], r[j*DIL + t], acc[t]);
    }
    *(float4*)&out[((size_t)bc << 10) + y*32 + x0] = make_float4(acc[0],acc[1],acc[2],acc[3]);
}

// ---------------- pointwise conv 128->128, f32x2, packed weights -------------
// 256 threads; block = 64co x 8y x 32x; thread = 8co x 4y x 2x; warp = co-group
__global__ void __launch_bounds__(256, 2) pw_conv_kernel(const float* __restrict__ in,
                                                         float* __restrict__ out,
                                                         const float* __restrict__ w,
                                                         int oslot) {
    __shared__ __align__(16) float s_in[16][8][32];   // 16 KB
    __shared__ ull s_wp[64][16];                      // (w,w) pairs, 8 KB
    int tid = threadIdx.x;
    int co0 = blockIdx.x * 64, y0 = blockIdx.y * 8, b = blockIdx.z;
    int xp = tid & 15, yh = (tid >> 4) & 1, cg = tid >> 5;
    ull acc[8][4];
    #pragma unroll
    for (int j = 0; j < 8; j++)
        #pragma unroll
        for (int k = 0; k < 4; k++) acc[j][k] = 0ull;

    for (int cc = 0; cc < CP; cc += 16) {
        { int co = tid >> 2, cq = (tid & 3) * 4;
          float4 v = *(const float4*)&w[(size_t)(co0+co)*CP + cc + cq];
          s_wp[co][cq+0] = pack2(v.x, v.x);
          s_wp[co][cq+1] = pack2(v.y, v.y);
          s_wp[co][cq+2] = pack2(v.z, v.z);
          s_wp[co][cq+3] = pack2(v.w, v.w); }
        #pragma unroll
        for (int i = tid; i < 1024; i += 256) {       // float4 units
            int ci = i >> 6, rem = i & 63;
            int y = rem >> 3, h = rem & 7;
            *(float4*)&s_in[ci][y][h*4] =
                *(const float4*)&in[(((size_t)b*CP + cc+ci)*HH + y0+y)*WW + h*4];
        }
        __syncthreads();
        #pragma unroll
        for (int ci = 0; ci < 16; ci++) {
            ull iv[4];
            #pragma unroll
            for (int k = 0; k < 4; k++) iv[k] = *(const ull*)&s_in[ci][yh*4 + k][2*xp];
            #pragma unroll
            for (int j = 0; j < 8; j++) {
                ull wv2 = s_wp[cg*8 + j][ci];
                #pragma unroll
                for (int k = 0; k < 4; k++) ffma2(acc[j][k], wv2, iv[k]);
            }
        }
        __syncthreads();
    }
    #pragma unroll
    for (int j = 0; j < 8; j++) {
        int co = co0 + cg*8 + j;
        float s = 0.f, s2 = 0.f;
        #pragma unroll
        for (int k = 0; k < 4; k++) {
            float v0, v1; unpack2(acc[j][k], v0, v1);
            *(float2*)&out[(((size_t)b*CP + co)*HH + y0 + yh*4 + k)*WW + 2*xp] = make_float2(v0, v1);
            s += v0 + v1; s2 += v0*v0 + v1*v1;
        }
        #pragma unroll
        for (int o = 16; o > 0; o >>= 1) {
            s  += __shfl_xor_sync(0xffffffffu, s,  o);
            s2 += __shfl_xor_sync(0xffffffffu, s2, o);
        }
        if ((tid & 31) == 0 && oslot >= 0) {
            atomicAdd(&g_ssum [oslot*CP + co], (double)s);
            atomicAdd(&g_ssum2[oslot*CP + co], (double)s2);
        }
    }
}

// ---------------- 1x7 conv (KW=7, pad 3), relu-in, dual-shifted copies -------
// Dynamic smem: s0[16][8][40], s1 (shifted left 1), s_wp[64][16][7] = 96 KB.
// 256 threads; block = 64co x 8y x 32x; thread = 8co x 4y(half) x 2x.
// Every input pair is an ALIGNED LDS.64: even kw from s0, odd kw from s1.
// launch_bounds minBlocks=2: occupancy is register-capped otherwise (R11: 132 regs -> 1 block/SM).
__global__ void __launch_bounds__(256, 2) conv1x7_kernel(const float* __restrict__ in,
                                                         float* __restrict__ out,
                                                         const float* __restrict__ w) {
    extern __shared__ __align__(16) char dsm[];
    float* s0  = (float*)dsm;                  // 16*8*40 floats
    float* s1  = s0 + 16*8*40;                 // shifted copy
    ull*   swp = (ull*)(s1 + 16*8*40);         // [64][16][7]
    int tid = threadIdx.x;
    int co0 = blockIdx.x * 64, y0 = blockIdx.y * 8, b = blockIdx.z;
    int xp = tid & 15, yh = (tid >> 4) & 1, cg = tid >> 5;
    ull acc[8][4];
    #pragma unroll
    for (int j = 0; j < 8; j++)
        #pragma unroll
        for (int k = 0; k < 4; k++) acc[j][k] = 0ull;

    for (int cc = 0; cc < CP; cc += 16) {
        for (int i = tid; i < 16*8*40; i += 256) {
            int ci = i / 320, rem = i - ci*320;
            int yy = rem / 40, q = rem - yy*40;
            int x = q - 3;
            float v = 0.f;
            if (x >= 0 && x < WW)
                v = fmaxf(in[(((size_t)b*CP + cc+ci)*HH + y0+yy)*WW + x], 0.f);
            int o = (ci*8 + yy)*40 + q;
            s0[o] = v;
            if (q > 0) s1[o - 1] = v;
        }
        for (int i = tid; i < 64*16*7; i += 256) {
            int co = i / 112, rem = i - co*112;
            int ci = rem / 7, kw = rem - ci*7;
            float v = w[((size_t)(co0+co)*CP + cc+ci)*7 + kw];
            swp[(co*16 + ci)*7 + kw] = pack2(v, v);
        }
        __syncthreads();
        #pragma unroll
        for (int ci = 0; ci < 16; ci++) {
            int rb = (ci*8 + yh*4)*40;
            #pragma unroll
            for (int kw = 0; kw < 7; kw++) {
                const float* src = (kw & 1) ? s1 : s0;
                int qq = 2*xp + kw - (kw & 1);       // even -> aligned LDS.64
                ull iv[4];
                #pragma unroll
                for (int k = 0; k < 4; k++) iv[k] = *(const ull*)&src[rb + k*40 + qq];
                #pragma unroll
                for (int j = 0; j < 8; j++) {
                    ull wv2 = swp[((cg*8 + j)*16 + ci)*7 + kw];
                    #pragma unroll
                    for (int k = 0; k < 4; k++) ffma2(acc[j][k], wv2, iv[k]);
                }
            }
        }
        __syncthreads();
    }
    #pragma unroll
    for (int j = 0; j < 8; j++) {
        int co = co0 + cg*8 + j;
        #pragma unroll
        for (int k = 0; k < 4; k++) {
            float v0, v1; unpack2(acc[j][k], v0, v1);
            *(float2*)&out[(((size_t)b*CP + co)*HH + y0 + yh*4 + k)*WW + 2*xp] = make_float2(v0, v1);
        }
    }
}

// ---------------- 7x1 conv (KH=7, pad 3), packed weights, ci=16, stats -------
// Dynamic smem: s_in[16][14][32] + s_wp[64][16][7] = 84 KB. minBlocks=2.
__global__ void __launch_bounds__(256, 2) conv7x1_kernel(const float* __restrict__ in,
                                                         float* __restrict__ out,
                                                         const float* __restrict__ w,
                                                         int oslot) {
    extern __shared__ __align__(16) char dsm[];
    float* sin = (float*)dsm;                  // 16*14*32 floats
    ull*   swp = (ull*)(sin + 16*14*32);       // [64][16][7]
    int tid = threadIdx.x;
    int co0 = blockIdx.x * 64, y0 = blockIdx.y * 8, b = blockIdx.z;
    int xp = tid & 15, yh = (tid >> 4) & 1, cg = tid >> 5;
    ull acc[8][4];
    #pragma unroll
    for (int j = 0; j < 8; j++)
        #pragma unroll
        for (int k = 0; k < 4; k++) acc[j][k] = 0ull;

    for (int cc = 0; cc < CP; cc += 16) {
        for (int i = tid; i < 16*14*32; i += 256) {
            int ci = i / 448, rem = i - ci*448;
            int r = rem >> 5, q = rem & 31;
            int yy = y0 + r - 3;
            float v = 0.f;
            if (yy >= 0 && yy < HH) v = in[(((size_t)b*CP + cc+ci)*HH + yy)*WW + q];
            sin[(ci*14 + r)*32 + q] = v;
        }
        for (int i = tid; i < 64*16*7; i += 256) {
            int co = i / 112, rem = i - co*112;
            int ci = rem / 7, kh = rem - ci*7;
            float v = w[((size_t)(co0+co)*CP + cc+ci)*7 + kh];
            swp[(co*16 + ci)*7 + kh] = pack2(v, v);
        }
        __syncthreads();
        #pragma unroll
        for (int ci = 0; ci < 16; ci++) {
            ull iv[10];
            #pragma unroll
            for (int r = 0; r < 10; r++)
                iv[r] = *(const ull*)&sin[(ci*14 + yh*4 + r)*32 + 2*xp];
            #pragma unroll
            for (int kh = 0; kh < 7; kh++) {
                #pragma unroll
                for (int j = 0; j < 8; j++) {
                    ull wv2 = swp[((cg*8 + j)*16 + ci)*7 + kh];
                    #pragma unroll
                    for (int k = 0; k < 4; k++) ffma2(acc[j][k], wv2, iv[k + kh]);
                }
            }
        }
        __syncthreads();
    }
    #pragma unroll
    for (int j = 0; j < 8; j++) {
        int co = co0 + cg*8 + j;
        float s = 0.f, s2 = 0.f;
        #pragma unroll
        for (int k = 0; k < 4; k++) {
            float v0, v1; unpack2(acc[j][k], v0, v1);
            *(float2*)&out[(((size_t)b*CP + co)*HH + y0 + yh*4 + k)*WW + 2*xp] = make_float2(v0, v1);
            s += v0 + v1; s2 += v0*v0 + v1*v1;
        }
        #pragma unroll
        for (int o = 16; o > 0; o >>= 1) {
            s  += __shfl_xor_sync(0xffffffffu, s,  o);
            s2 += __shfl_xor_sync(0xffffffffu, s2, o);
        }
        if ((tid & 31) == 0 && oslot >= 0) {
            atomicAdd(&g_ssum [oslot*CP + co], (double)s);
            atomicAdd(&g_ssum2[oslot*CP + co], (double)s2);
        }
    }
}

// ---------------- final combine + scatter (float4) ----------------------------
__global__ void combine_kernel(const float* __restrict__ wv, float* __restrict__ out) {
    int n4 = blockIdx.x * 256 + threadIdx.x;   // < NSEL/4
    int n = n4 << 2;
    int b = n >> 17, p = (n >> 10) & 127, hw = n & 1023;
    float m0 = g_meanv[0*CP+p],  r0 = g_rstdv[0*CP+p];
    float m1 = g_meanv[1*CP+p],  r1 = g_rstdv[1*CP+p];
    float m3 = g_meanv[3*CP+p],  r3 = g_rstdv[3*CP+p];
    float m5 = g_meanv[5*CP+p],  r5 = g_rstdv[5*CP+p];
    float m7 = g_meanv[7*CP+p],  r7 = g_rstdv[7*CP+p];
    float m8 = g_meanv[8*CP+p],  r8 = g_rstdv[8*CP+p];
    float m9 = g_meanv[9*CP+p],  r9 = g_rstdv[9*CP+p];
    float mA = g_meanv[10*CP+p], rA = g_rstdv[10*CP+p];
    float w1=wv[1],w2=wv[2],w3=wv[3],w4=wv[4],w5=wv[5],w6=wv[6],w7=wv[7],w8=wv[8],w9=wv[9];
    float a[4] = {0.f,0.f,0.f,0.f};
    { float4 v = *(const float4*)&g_bmax[n];  const float* q=(const float*)&v;
      #pragma unroll
      for (int t=0;t<4;t++) a[t] += w1*(q[t]-m0)*r0; }
    { float4 v = *(const float4*)&g_bavg[n];  const float* q=(const float*)&v;
      #pragma unroll
      for (int t=0;t<4;t++) a[t] += w2*(q[t]-m1)*r1; }
    { float4 v = *(const float4*)&g_xtemp[n]; const float* q=(const float*)&v;
      #pragma unroll
      for (int t=0;t<4;t++) a[t] += w3*q[t]; }
    { float4 v = *(const float4*)&g_s3[n];    const float* q=(const float*)&v;
      #pragma unroll
      for (int t=0;t<4;t++) a[t] += w4*(q[t]-m3)*r3; }
    { float4 v = *(const float4*)&g_s5[n];    const float* q=(const float*)&v;
      #pragma unroll
      for (int t=0;t<4;t++) a[t] += w5*(q[t]-m5)*r5; }
    { float4 v = *(const float4*)&g_s7[n];    const float* q=(const float*)&v;
      #pragma unroll
      for (int t=0;t<4;t++) a[t] += w6*(q[t]-m7)*r7; }
    { float4 v = *(const float4*)&g_d3[n];    const float* q=(const float*)&v;
      #pragma unroll
      for (int t=0;t<4;t++) a[t] += w7*(q[t]-m8)*r8; }
    { float4 v = *(const float4*)&g_d5[n];    const float* q=(const float*)&v;
      #pragma unroll
      for (int t=0;t<4;t++) a[t] += w8*(q[t]-m9)*r9; }
    { float4 v = *(const float4*)&g_c7[n];    const float* q=(const float*)&v;
      #pragma unroll
      for (int t=0;t<4;t++) a[t] += w9*(q[t]-mA)*rA; }
    int cs = g_idx[p];
    *(float4*)&out[(((size_t)b*C + cs) << 10) + hw] = make_float4(a[0],a[1],a[2],a[3]);
}

// =============================================================================
extern "C" void kernel_launch(void* const* d_in, const int* in_sizes, int n_in,
                              void* d_out, int out_size) {
    const float* x        = (const float*)d_in[0];
    const float* weights  = (const float*)d_in[1];
    const float* wall     = (const float*)d_in[2];
    const float* w_fc1    = (const float*)d_in[3];
    const float* w_fc2    = (const float*)d_in[4];
    const float* sep3_dw1 = (const float*)d_in[5];
    const float* sep3_pw1 = (const float*)d_in[6];
    const float* sep3_dw2 = (const float*)d_in[7];
    const float* sep3_pw2 = (const float*)d_in[8];
    const float* sep5_dw1 = (const float*)d_in[9];
    const float* sep5_pw1 = (const float*)d_in[10];
    const float* sep5_dw2 = (const float*)d_in[11];
    const float* sep5_pw2 = (const float*)d_in[12];
    const float* sep7_dw1 = (const float*)d_in[13];
    const float* sep7_pw1 = (const float*)d_in[14];
    const float* sep7_dw2 = (const float*)d_in[15];
    const float* sep7_pw2 = (const float*)d_in[16];
    const float* dil3_dw  = (const float*)d_in[17];
    const float* dil3_pw  = (const float*)d_in[18];
    const float* dil5_dw  = (const float*)d_in[19];
    const float* dil5_pw  = (const float*)d_in[20];
    const float* w_1x7    = (const float*)d_in[21];
    const float* w_7x1    = (const float*)d_in[22];
    float* out = (float*)d_out;

    // Resolve REAL device addresses (host shadow symbols are ATS garbage on GB300).
    float *t_xtemp,*t_1,*t_2,*t_bmax,*t_bavg,*t_s3,*t_s5,*t_s7,*t_d3,*t_d5,*t_c7;
    { void* p;
      cudaGetSymbolAddress(&p, g_xtemp); t_xtemp=(float*)p;
      cudaGetSymbolAddress(&p, g_t1);    t_1    =(float*)p;
      cudaGetSymbolAddress(&p, g_t2);    t_2    =(float*)p;
      cudaGetSymbolAddress(&p, g_bmax);  t_bmax =(float*)p;
      cudaGetSymbolAddress(&p, g_bavg);  t_bavg =(float*)p;
      cudaGetSymbolAddress(&p, g_s3);    t_s3   =(float*)p;
      cudaGetSymbolAddress(&p, g_s5);    t_s5   =(float*)p;
      cudaGetSymbolAddress(&p, g_s7);    t_s7   =(float*)p;
      cudaGetSymbolAddress(&p, g_d3);    t_d3   =(float*)p;
      cudaGetSymbolAddress(&p, g_d5);    t_d5   =(float*)p;
      cudaGetSymbolAddress(&p, g_c7);    t_c7   =(float*)p; }

    // Dynamic smem opt-in for the 7-convs (idempotent; capture-safe: not a stream op)
    const int SM1X7 = (16*8*40*2)*4 + 64*16*7*8;   // 96 KB
    const int SM7X1 = (16*14*32)*4 + 64*16*7*8;    // 84 KB
    cudaFuncSetAttribute(conv1x7_kernel, cudaFuncAttributeMaxDynamicSharedMemorySize, SM1X7);
    cudaFuncSetAttribute(conv7x1_kernel, cudaFuncAttributeMaxDynamicSharedMemorySize, SM7X1);

    const int GSEL4 = NSEL / 1024;   // 8192
    const int GALL4 = NALL / 1024;   // 32768
    dim3 gcv(2, 4, B);               // 64co x 8y tiles (pw + 7-convs)
    const int GDW = B * CP;          // 8192

    // 0-2: dependency prefix for conv1x7
    attn_fused_kernel<<<B, 512>>>(x, w_fc1, wall, w_fc2);
    slist_topk_kernel<<<1, C>>>();
    gather4_kernel<<<GSEL4, 256>>>(x);

    // 3: conv1x7 (ncu samples launch index 3)
    conv1x7_kernel<<<gcv, 256, SM1X7>>>(t_xtemp, t_1, w_1x7);
    conv7x1_kernel<<<gcv, 256, SM7X1>>>(t_1, t_c7, w_7x1, 10);

    // independent passes
    scale4_kernel<<<GALL4, 256>>>(x, out);
    pool3f_kernel<<<GDW, 256>>>(t_xtemp, t_bmax, t_bavg);

    // sep convs: slots mid/fin = (2,3) (4,5) (6,7)
    dw_conv_kernel<3,1,1><<<GDW, 256>>>(t_xtemp, t_1, sep3_dw1, 0);
    pw_conv_kernel<<<gcv, 256>>>(t_1, t_2, sep3_pw1, 2);
    dw_conv_kernel<3,1,2><<<GDW, 256>>>(t_2, t_1, sep3_dw2, 2);
    pw_conv_kernel<<<gcv, 256>>>(t_1, t_s3, sep3_pw2, 3);

    dw_conv_kernel<5,1,1><<<GDW, 256>>>(t_xtemp, t_1, sep5_dw1, 0);
    pw_conv_kernel<<<gcv, 256>>>(t_1, t_2, sep5_pw1, 4);
    dw_conv_kernel<5,1,2><<<GDW, 256>>>(t_2, t_1, sep5_dw2, 4);
    pw_conv_kernel<<<gcv, 256>>>(t_1, t_s5, sep5_pw2, 5);

    dw_conv_kernel<7,1,1><<<GDW, 256>>>(t_xtemp, t_1, sep7_dw1, 0);
    pw_conv_kernel<<<gcv, 256>>>(t_1, t_2, sep7_pw1, 6);
    dw_conv_kernel<7,1,2><<<GDW, 256>>>(t_2, t_1, sep7_dw2, 6);
    pw_conv_kernel<<<gcv, 256>>>(t_1, t_s7, sep7_pw2, 7);

    // dilated convs
    dw_conv_kernel<3,2,1><<<GDW, 256>>>(t_xtemp, t_1, dil3_dw, 0);
    pw_conv_kernel<<<gcv, 256>>>(t_1, t_d3, dil3_pw, 8);
    dw_conv_kernel<5,2,1><<<GDW, 256>>>(t_xtemp, t_1, dil5_dw, 0);
    pw_conv_kernel<<<gcv, 256>>>(t_1, t_d5, dil5_pw, 9);

    // finalize all stats, combine, scatter
    finalize_kernel<<<NSLOT, 128>>>();
    combine_kernel<<<GSEL4, 256>>>(weights, out);
}

// round 16
// speedup vs baseline: 1.3298x; 1.0739x over previous
#include <cuda_runtime.h>
#include <cuda_bf16.h>
#include <math.h>
#include <stdint.h>

#define B   64
#define C   512
#define CP  128
#define HH  32
#define WW  32
#define HW  1024
#define NSEL (B*CP*HW)       // 8388608
#define NALL (B*C*HW)        // 33554432
#define NSLOT 11

// ---------------- scratch (device globals; no allocs allowed) ----------------
__device__ float g_ca[B*C];
__device__ int   g_idx[CP];
__device__ float g_xtemp[NSEL];
__device__ float g_t1[NSEL];
__device__ float g_t2[NSEL];
__device__ float g_bmax[NSEL];
__device__ float g_bavg[NSEL];
__device__ float g_s3[NSEL];
__device__ float g_s5[NSEL];
__device__ float g_s7[NSEL];
__device__ float g_d3[NSEL];
__device__ float g_d5[NSEL];
__device__ float g_c7[NSEL];
__device__ double g_ssum [NSLOT*CP];
__device__ double g_ssum2[NSLOT*CP];
__device__ float  g_meanv[NSLOT*CP];
__device__ float  g_rstdv[NSLOT*CP];

// slots: 0 max, 1 avg, 2 sep3mid, 3 sep3fin, 4 sep5mid, 5 sep5fin,
//        6 sep7mid, 7 sep7fin, 8 dil3, 9 dil5, 10 c7

typedef unsigned long long ull;
__device__ __forceinline__ ull pack2(float a, float b){
    ull r; asm("mov.b64 %0,{%1,%2};":"=l"(r):"f"(a),"f"(b)); return r;
}
__device__ __forceinline__ void unpack2(ull v, float&a, float&b){
    asm("mov.b64 {%0,%1},%2;":"=f"(a),"=f"(b):"l"(v));
}
__device__ __forceinline__ void ffma2(ull&d, ull a, ull b){
    asm("fma.rn.f32x2 %0,%1,%2,%0;":"+l"(d):"l"(a),"l"(b));
}
__device__ __forceinline__ uint32_t smem_u32(const void* p){
    uint32_t a;
    asm("{ .reg .u64 t; cvta.to.shared.u64 t, %1; cvt.u32.u64 %0, t; }":"=r"(a):"l"(p));
    return a;
}
// ---- mma.sync helpers (sm_80 PTX; legal on compute_103, unlike tcgen05) -----
__device__ __forceinline__ void ldsm_x4(uint32_t&a0,uint32_t&a1,uint32_t&a2,uint32_t&a3,uint32_t addr){
    asm volatile("ldmatrix.sync.aligned.m8n8.x4.shared.b16 {%0,%1,%2,%3},[%4];"
        :"=r"(a0),"=r"(a1),"=r"(a2),"=r"(a3):"r"(addr));
}
__device__ __forceinline__ void ldsm_x2t(uint32_t&b0,uint32_t&b1,uint32_t addr){
    asm volatile("ldmatrix.sync.aligned.m8n8.x2.trans.shared.b16 {%0,%1},[%2];"
        :"=r"(b0),"=r"(b1):"r"(addr));
}
__device__ __forceinline__ void mma_bf16(float&d0,float&d1,float&d2,float&d3,
                                         uint32_t a0,uint32_t a1,uint32_t a2,uint32_t a3,
                                         uint32_t b0,uint32_t b1){
    asm volatile("mma.sync.aligned.m16n8k16.row.col.f32.bf16.bf16.f32 "
        "{%0,%1,%2,%3},{%4,%5,%6,%7},{%8,%9},{%0,%1,%2,%3};"
        :"+f"(d0),"+f"(d1),"+f"(d2),"+f"(d3)
        :"r"(a0),"r"(a1),"r"(a2),"r"(a3),"r"(b0),"r"(b1));
}

// ---------------- 0. fused global pooling + attention MLP (+ stats zero) -----
__global__ void __launch_bounds__(512) attn_fused_kernel(
        const float* __restrict__ x, const float* __restrict__ fc1,
        const float* __restrict__ wa, const float* __restrict__ fc2) {
    int b = blockIdx.x, tid = threadIdx.x;     // 512 threads
    __shared__ float pooled[1024];
    __shared__ float red[16];
    __shared__ float s_y[10], s_A[100], s_y2[10];
    if (b == 0) {
        for (int i = tid; i < NSLOT*CP; i += 512) { g_ssum[i] = 0.0; g_ssum2[i] = 0.0; }
    }
    int w = tid >> 5, l = tid & 31;
    for (int j = 0; j < 32; j++) {
        int c = w*32 + j;
        const float* p = x + ((size_t)(b*C + c) << 10);
        float s = 0.f, m = -INFINITY;
        #pragma unroll 4
        for (int k = 0; k < 32; k++) { float v = p[l + 32*k]; s += v; m = fmaxf(m, v); }
        #pragma unroll
        for (int o = 16; o > 0; o >>= 1) {
            s += __shfl_xor_sync(0xffffffffu, s, o);
            m = fmaxf(m, __shfl_xor_sync(0xffffffffu, m, o));
        }
        if (l == 0) { pooled[c] = s * (1.f/1024.f); pooled[C + c] = m; }
    }
    __syncthreads();
    for (int j = 0; j < 10; j++) {
        float local = pooled[tid] * fc1[j*2*C + tid] + pooled[512 + tid] * fc1[j*2*C + 512 + tid];
        #pragma unroll
        for (int o = 16; o > 0; o >>= 1) local += __shfl_xor_sync(0xffffffffu, local, o);
        if (l == 0) red[w] = local;
        __syncthreads();
        if (tid == 0) { float t = 0.f; for (int q = 0; q < 16; q++) t += red[q]; s_y[j] = t; }
        __syncthreads();
    }
    if (tid < 100) {
        int j = tid / 10, k = tid % 10;
        float a = 0.f;
        for (int m = 0; m < 14; m++) a += wa[m*10 + j] * wa[m*10 + k];
        s_A[tid] = a;
    }
    __syncthreads();
    if (tid < 10) {
        float v = 0.f;
        for (int k = 0; k < 10; k++) v += s_y[k] * s_A[tid*10 + k];
        s_y2[tid] = fmaxf(v, 0.f);
    }
    __syncthreads();
    {
        int c = tid;
        float v = 0.f;
        for (int j = 0; j < 10; j++) v += s_y2[j] * fc2[c*10 + j];
        g_ca[b*C + c] = 1.f / (1.f + expf(-v));
    }
}

// ---------------- 1. slist + exact lax.top_k ordering (merged) ----------------
__global__ void slist_topk_kernel() {
    __shared__ float v[C];
    int c = threadIdx.x;                       // 512
    float s = 0.f;
    for (int b = 0; b < B; b++) s += g_ca[b*C + c];
    v[c] = s; __syncthreads();
    float mv = v[c];
    int rank = 0;
    for (int i = 0; i < C; i++) {
        float o = v[i];
        rank += (o > mv) || (o == mv && i < c);
    }
    if (rank < CP) g_idx[rank] = c;
}

// ---------------- gather xtemp (for identity branch in combine) --------------
__global__ void gather4_kernel(const float* __restrict__ x) {
    int n4 = blockIdx.x * 256 + threadIdx.x;   // < NSEL/4
    int n = n4 << 2;
    int b = n >> 17, p = (n >> 10) & 127, hw = n & 1023;
    int cs = g_idx[p];
    float ca = g_ca[b*C + cs];
    float4 v = *(const float4*)&x[(((size_t)b*C + cs) << 10) + hw];
    v.x *= ca; v.y *= ca; v.z *= ca; v.w *= ca;
    *(float4*)&g_xtemp[n] = v;
}

// ---------------- scale x by ca into d_out (float4) ----------------
__global__ void scale4_kernel(const float* __restrict__ x, float* __restrict__ out) {
    int n4 = blockIdx.x * 256 + threadIdx.x;   // < NALL/4
    int n = n4 << 2;
    float ca = g_ca[n >> 10];
    float4 v = *(const float4*)&x[n];
    v.x *= ca; v.y *= ca; v.z *= ca; v.w *= ca;
    *(float4*)&out[n] = v;
}

// ---------------- fused 3x3 max+avg pool + stats (gathers from x) ------------
__global__ void __launch_bounds__(256) pool3f_kernel(const float* __restrict__ x,
                                                     float* __restrict__ omax,
                                                     float* __restrict__ oavg) {
    __shared__ float s[34][35];
    __shared__ float rsm[8][4];
    int bc = blockIdx.x;
    int tid = threadIdx.x;
    int b = bc >> 7, p = bc & 127;
    int cs = g_idx[p];
    float ca = g_ca[b*C + cs];
    const float* ip = x + ((size_t)(b*C + cs) << 10);
    for (int i = tid; i < 34*34; i += 256) {
        int r = i / 34, q = i - r*34;
        int y = r - 1, xx = q - 1;
        s[r][q] = (y >= 0 && y < 32 && xx >= 0 && xx < 32) ? ip[y*32 + xx] * ca : 0.f;
    }
    __syncthreads();
    int y = tid >> 3, x0 = (tid & 7) * 4;
    float vmax[4], vavg[4];
    int yl = (y > 0 ? y-1 : 0), yhh = (y < 31 ? y+1 : 31);
    int ch = yhh - yl + 1;
    #pragma unroll
    for (int t = 0; t < 4; t++) {
        int xx = x0 + t;
        float m = -INFINITY, sm = 0.f;
        #pragma unroll
        for (int dy = 0; dy < 3; dy++) {
            int yy = y + dy;
            bool yok = (yy >= 1 && yy <= 32);
            #pragma unroll
            for (int dx = 0; dx < 3; dx++) {
                int xq = xx + dx;
                float v = s[yy][xq];
                sm += v;
                if (yok && xq >= 1 && xq <= 32) m = fmaxf(m, v);
            }
        }
        int xl = (xx > 0 ? xx-1 : 0), xh = (xx < 31 ? xx+1 : 31);
        int cnt = ch * (xh - xl + 1);
        vmax[t] = m; vavg[t] = sm / (float)cnt;
    }
    size_t base = ((size_t)bc << 10) + y*32 + x0;
    *(float4*)&omax[base] = make_float4(vmax[0],vmax[1],vmax[2],vmax[3]);
    *(float4*)&oavg[base] = make_float4(vavg[0],vavg[1],vavg[2],vavg[3]);
    float sM=0,sM2=0,sA=0,sA2=0;
    #pragma unroll
    for (int t = 0; t < 4; t++) { sM += vmax[t]; sM2 += vmax[t]*vmax[t]; sA += vavg[t]; sA2 += vavg[t]*vavg[t]; }
    #pragma unroll
    for (int o = 16; o > 0; o >>= 1) {
        sM  += __shfl_xor_sync(0xffffffffu, sM,  o);
        sM2 += __shfl_xor_sync(0xffffffffu, sM2, o);
        sA  += __shfl_xor_sync(0xffffffffu, sA,  o);
        sA2 += __shfl_xor_sync(0xffffffffu, sA2, o);
    }
    int w = tid >> 5;
    if ((tid & 31) == 0) { rsm[w][0]=sM; rsm[w][1]=sM2; rsm[w][2]=sA; rsm[w][3]=sA2; }
    __syncthreads();
    if (tid == 0) {
        float a=0,b2=0,c2=0,d2=0;
        for (int q = 0; q < 8; q++) { a+=rsm[q][0]; b2+=rsm[q][1]; c2+=rsm[q][2]; d2+=rsm[q][3]; }
        atomicAdd(&g_ssum [0*CP + p], (double)a);
        atomicAdd(&g_ssum2[0*CP + p], (double)b2);
        atomicAdd(&g_ssum [1*CP + p], (double)c2);
        atomicAdd(&g_ssum2[1*CP + p], (double)d2);
    }
}

// ---------------- finalize stats ----------------
__global__ void finalize_kernel() {
    int s = blockIdx.x, c = threadIdx.x;       // 11 x 128
    double su = g_ssum[s*CP+c], sq = g_ssum2[s*CP+c];
    double m  = su * (1.0/65536.0);
    double var = sq * (1.0/65536.0) - m*m;
    g_meanv[s*CP+c] = (float)m;
    g_rstdv[s*CP+c] = (float)rsqrt(var + 1e-5);
}

// ------- depthwise conv; TRANS: 1 relu, 2 bn+relu; GATHER: read x via idx ----
template<int K, int DIL, int TRANS, int GATHER>
__global__ void __launch_bounds__(256) dw_conv_kernel(const float* __restrict__ in,
                                                      float* __restrict__ out,
                                                      const float* __restrict__ w,
                                                      int islot) {
    constexpr int P  = (DIL==1) ? (K/2) : (K-1);
    constexpr int SW = 32 + 2*P;
    constexpr int SWP = SW + 1;
    constexpr int SPAN = 4 + (K-1)*DIL;
    __shared__ float s[SW][SWP];
    __shared__ float s_mr[2];
    int bc = blockIdx.x;
    int b = bc >> 7, c = bc & 127;
    int tid = threadIdx.x;
    if (TRANS == 2 && tid == 0) {
        double su = g_ssum[islot*CP + c], sq = g_ssum2[islot*CP + c];
        double m = su * (1.0/65536.0);
        double var = sq * (1.0/65536.0) - m*m;
        s_mr[0] = (float)m; s_mr[1] = (float)rsqrt(var + 1e-5);
    }
    if (TRANS == 2) __syncthreads();
    float mean = 0.f, rstd = 1.f;
    if (TRANS == 2) { mean = s_mr[0]; rstd = s_mr[1]; }
    const float* ip;
    float ca = 1.f;
    if (GATHER) {
        int cs = g_idx[c];
        ca = g_ca[b*C + cs];
        ip = in + ((size_t)(b*C + cs) << 10);
    } else {
        ip = in + ((size_t)bc << 10);
    }
    for (int i = tid; i < SW*SW; i += 256) {
        int r = i / SW, q = i - r*SW;
        int y = r - P, xx = q - P;
        float v = 0.f;
        if (y >= 0 && y < 32 && xx >= 0 && xx < 32) {
            v = ip[y*32 + xx];
            if (GATHER) v *= ca;
            if (TRANS == 1) v = fmaxf(v, 0.f);
            else if (TRANS == 2) v = fmaxf((v - mean)*rstd, 0.f);
        }
        s[r][q] = v;
    }
    float wr[K][K];
    #pragma unroll
    for (int i = 0; i < K; i++)
        #pragma unroll
        for (int j = 0; j < K; j++) wr[i][j] = w[(c*K + i)*K + j];
    __syncthreads();
    int y = tid >> 3, x0 = (tid & 7) * 4;
    float acc[4] = {0.f, 0.f, 0.f, 0.f};
    #pragma unroll
    for (int i = 0; i < K; i++) {
        float r[SPAN];
        #pragma unroll
        for (int q = 0; q < SPAN; q++) r[q] = s[y + i*DIL][x0 + q];
        #pragma unroll
        for (int j = 0; j < K; j++)
            #pragma unroll
            for (int t = 0; t < 4; t++) acc[t] = fmaf(wr[i][j], r[j*DIL + t], acc[t]);
    }
    *(float4*)&out[((size_t)bc << 10) + y*32 + x0] = make_float4(acc[0],acc[1],acc[2],acc[3]);
}

// -------- pointwise conv 128->128 via mma.sync bf16-split (3 passes) ---------
// Block = (b, 64 spatial) tile; grid (16, B). 256 thr = 8 warps; warp owns 16 co.
// Smem: Whi/Wlo [128][136]bf16 (272B rows), Xhi/Xlo [128ci][72n]bf16 (144B rows).
// A-frag: ldmatrix.x4 (row-major W); B-frag: ldmatrix.x2.trans (k-major X).
__global__ void __launch_bounds__(256, 2) pw_mma_kernel(const float* __restrict__ in,
                                                        float* __restrict__ out,
                                                        const float* __restrict__ w,
                                                        int oslot) {
    extern __shared__ __align__(16) char dsm[];
    const uint32_t oWlo = 34816u, oXhi = 69632u, oXlo = 88064u;
    int tid = threadIdx.x, lane = tid & 31, wid = tid >> 5;
    int tile = blockIdx.x;          // 0..15 -> spatial base tile*64
    int b = blockIdx.y;
    int sp0 = tile * 64;
    uint32_t sbase = smem_u32(dsm);

    // fill W hi/lo
    #pragma unroll
    for (int t = 0; t < 16; t++) {
        int idx4 = tid + t*256;                 // 0..4095
        int co = idx4 >> 5, c0 = (idx4 & 31) << 2;
        float4 v = *(const float4*)&w[(co << 7) + c0];
        __nv_bfloat16 h0=__float2bfloat16(v.x), h1=__float2bfloat16(v.y),
                      h2=__float2bfloat16(v.z), h3=__float2bfloat16(v.w);
        __nv_bfloat16 l0=__float2bfloat16(v.x-__bfloat162float(h0)),
                      l1=__float2bfloat16(v.y-__bfloat162float(h1)),
                      l2=__float2bfloat16(v.z-__bfloat162float(h2)),
                      l3=__float2bfloat16(v.w-__bfloat162float(h3));
        uint32_t off = (uint32_t)co*272u + (uint32_t)c0*2u;
        *(uint32_t*)(dsm + off)        = ((uint32_t)__bfloat16_as_ushort(h1)<<16) | __bfloat16_as_ushort(h0);
        *(uint32_t*)(dsm + off + 4)    = ((uint32_t)__bfloat16_as_ushort(h3)<<16) | __bfloat16_as_ushort(h2);
        *(uint32_t*)(dsm + oWlo + off)     = ((uint32_t)__bfloat16_as_ushort(l1)<<16) | __bfloat16_as_ushort(l0);
        *(uint32_t*)(dsm + oWlo + off + 4) = ((uint32_t)__bfloat16_as_ushort(l3)<<16) | __bfloat16_as_ushort(l2);
    }
    // fill X hi/lo  (k-major rows: X[ci][n], 72-elem rows)
    #pragma unroll
    for (int t = 0; t < 8; t++) {
        int idx4 = tid + t*256;                 // 0..2047
        int ci = idx4 >> 4, n0 = (idx4 & 15) << 2;
        float4 v = *(const float4*)&in[(((size_t)b*CP + ci) << 10) + sp0 + n0];
        __nv_bfloat16 h0=__float2bfloat16(v.x), h1=__float2bfloat16(v.y),
                      h2=__float2bfloat16(v.z), h3=__float2bfloat16(v.w);
        __nv_bfloat16 l0=__float2bfloat16(v.x-__bfloat162float(h0)),
                      l1=__float2bfloat16(v.y-__bfloat162float(h1)),
                      l2=__float2bfloat16(v.z-__bfloat162float(h2)),
                      l3=__float2bfloat16(v.w-__bfloat162float(h3));
        uint32_t off = (uint32_t)ci*144u + (uint32_t)n0*2u;
        *(uint32_t*)(dsm + oXhi + off)     = ((uint32_t)__bfloat16_as_ushort(h1)<<16) | __bfloat16_as_ushort(h0);
        *(uint32_t*)(dsm + oXhi + off + 4) = ((uint32_t)__bfloat16_as_ushort(h3)<<16) | __bfloat16_as_ushort(h2);
        *(uint32_t*)(dsm + oXlo + off)     = ((uint32_t)__bfloat16_as_ushort(l1)<<16) | __bfloat16_as_ushort(l0);
        *(uint32_t*)(dsm + oXlo + off + 4) = ((uint32_t)__bfloat16_as_ushort(l3)<<16) | __bfloat16_as_ushort(l2);
    }
    __syncthreads();

    float acc[8][4];
    #pragma unroll
    for (int nt = 0; nt < 8; nt++)
        #pragma unroll
        for (int q = 0; q < 4; q++) acc[nt][q] = 0.f;

    uint32_t arow = (uint32_t)(wid*16 + (lane & 15));
    uint32_t ahalf = (uint32_t)(lane >> 4);
    uint32_t bro = (uint32_t)(lane & 15) * 144u;

    #pragma unroll
    for (int pass = 0; pass < 3; pass++) {
        uint32_t aaddr = sbase + (pass == 2 ? oWlo : 0u) + arow*272u + ahalf*16u;
        uint32_t bbase = sbase + (pass == 1 ? oXlo : oXhi) + bro;
        #pragma unroll
        for (int k = 0; k < 8; k++) {
            uint32_t a0,a1,a2,a3;
            ldsm_x4(a0,a1,a2,a3, aaddr + (uint32_t)k*32u);
            uint32_t brow = bbase + (uint32_t)k*2304u;   // 16 rows * 144B
            #pragma unroll
            for (int nt = 0; nt < 8; nt++) {
                uint32_t b0,b1;
                ldsm_x2t(b0,b1, brow + (uint32_t)nt*16u);
                mma_bf16(acc[nt][0],acc[nt][1],acc[nt][2],acc[nt][3], a0,a1,a2,a3, b0,b1);
            }
        }
    }

    // epilogue: write D + fused per-channel stats
    int coA = wid*16 + (lane >> 2);
    int coB = coA + 8;
    float sA=0.f, sA2=0.f, sB=0.f, sB2=0.f;
    #pragma unroll
    for (int nt = 0; nt < 8; nt++) {
        int sp = sp0 + nt*8 + (lane & 3)*2;
        *(float2*)&out[(((size_t)b*CP + coA) << 10) + sp] = make_float2(acc[nt][0], acc[nt][1]);
        *(float2*)&out[(((size_t)b*CP + coB) << 10) + sp] = make_float2(acc[nt][2], acc[nt][3]);
        sA += acc[nt][0] + acc[nt][1]; sA2 += acc[nt][0]*acc[nt][0] + acc[nt][1]*acc[nt][1];
        sB += acc[nt][2] + acc[nt][3]; sB2 += acc[nt][2]*acc[nt][2] + acc[nt][3]*acc[nt][3];
    }
    #pragma unroll
    for (int o = 1; o < 4; o <<= 1) {
        sA  += __shfl_xor_sync(0xffffffffu, sA,  o);
        sA2 += __shfl_xor_sync(0xffffffffu, sA2, o);
        sB  += __shfl_xor_sync(0xffffffffu, sB,  o);
        sB2 += __shfl_xor_sync(0xffffffffu, sB2, o);
    }
    if ((lane & 3) == 0 && oslot >= 0) {
        atomicAdd(&g_ssum [oslot*CP + coA], (double)sA);
        atomicAdd(&g_ssum2[oslot*CP + coA], (double)sA2);
        atomicAdd(&g_ssum [oslot*CP + coB], (double)sB);
        atomicAdd(&g_ssum2[oslot*CP + coB], (double)sB2);
    }
}

// ---------------- 1x7 conv (KW=7, pad 3), gathers from x, dual copies --------
__global__ void __launch_bounds__(256, 2) conv1x7_kernel(const float* __restrict__ x,
                                                         float* __restrict__ out,
                                                         const float* __restrict__ w) {
    extern __shared__ __align__(16) char dsm[];
    float* s0  = (float*)dsm;                  // 16*8*40 floats
    float* s1  = s0 + 16*8*40;                 // shifted copy
    ull*   swp = (ull*)(s1 + 16*8*40);         // [64][16][7]
    int tid = threadIdx.x;
    int co0 = blockIdx.x * 64, y0 = blockIdx.y * 8, b = blockIdx.z;
    int xp = tid & 15, yh = (tid >> 4) & 1, cg = tid >> 5;
    ull acc[8][4];
    #pragma unroll
    for (int j = 0; j < 8; j++)
        #pragma unroll
        for (int k = 0; k < 4; k++) acc[j][k] = 0ull;

    for (int cc = 0; cc < CP; cc += 16) {
        for (int i = tid; i < 16*8*40; i += 256) {
            int ci = i / 320, rem = i - ci*320;
            int yy = rem / 40, q = rem - yy*40;
            int xx = q - 3;
            float v = 0.f;
            if (xx >= 0 && xx < WW) {
                int cs = g_idx[cc + ci];
                float ca = g_ca[b*C + cs];
                v = fmaxf(x[(((size_t)b*C + cs)*HH + y0+yy)*WW + xx] * ca, 0.f);
            }
            int o = (ci*8 + yy)*40 + q;
            s0[o] = v;
            if (q > 0) s1[o - 1] = v;
        }
        for (int i = tid; i < 64*16*7; i += 256) {
            int co = i / 112, rem = i - co*112;
            int ci = rem / 7, kw = rem - ci*7;
            float v = w[((size_t)(co0+co)*CP + cc+ci)*7 + kw];
            swp[(co*16 + ci)*7 + kw] = pack2(v, v);
        }
        __syncthreads();
        #pragma unroll
        for (int ci = 0; ci < 16; ci++) {
            int rb = (ci*8 + yh*4)*40;
            #pragma unroll
            for (int kw = 0; kw < 7; kw++) {
                const float* src = (kw & 1) ? s1 : s0;
                int qq = 2*xp + kw - (kw & 1);
                ull iv[4];
                #pragma unroll
                for (int k = 0; k < 4; k++) iv[k] = *(const ull*)&src[rb + k*40 + qq];
                #pragma unroll
                for (int j = 0; j < 8; j++) {
                    ull wv2 = swp[((cg*8 + j)*16 + ci)*7 + kw];
                    #pragma unroll
                    for (int k = 0; k < 4; k++) ffma2(acc[j][k], wv2, iv[k]);
                }
            }
        }
        __syncthreads();
    }
    #pragma unroll
    for (int j = 0; j < 8; j++) {
        int co = co0 + cg*8 + j;
        #pragma unroll
        for (int k = 0; k < 4; k++) {
            float v0, v1; unpack2(acc[j][k], v0, v1);
            *(float2*)&out[(((size_t)b*CP + co)*HH + y0 + yh*4 + k)*WW + 2*xp] = make_float2(v0, v1);
        }
    }
}

// ---------------- 7x1 conv (KH=7, pad 3), packed weights, ci=16, stats -------
__global__ void __launch_bounds__(256, 2) conv7x1_kernel(const float* __restrict__ in,
                                                         float* __restrict__ out,
                                                         const float* __restrict__ w,
                                                         int oslot) {
    extern __shared__ __align__(16) char dsm[];
    float* sin = (float*)dsm;                  // 16*14*32 floats
    ull*   swp = (ull*)(sin + 16*14*32);       // [64][16][7]
    int tid = threadIdx.x;
    int co0 = blockIdx.x * 64, y0 = blockIdx.y * 8, b = blockIdx.z;
    int xp = tid & 15, yh = (tid >> 4) & 1, cg = tid >> 5;
    ull acc[8][4];
    #pragma unroll
    for (int j = 0; j < 8; j++)
        #pragma unroll
        for (int k = 0; k < 4; k++) acc[j][k] = 0ull;

    for (int cc = 0; cc < CP; cc += 16) {
        for (int i = tid; i < 16*14*32; i += 256) {
            int ci = i / 448, rem = i - ci*448;
            int r = rem >> 5, q = rem & 31;
            int yy = y0 + r - 3;
            float v = 0.f;
            if (yy >= 0 && yy < HH) v = in[(((size_t)b*CP + cc+ci)*HH + yy)*WW + q];
            sin[(ci*14 + r)*32 + q] = v;
        }
        for (int i = tid; i < 64*16*7; i += 256) {
            int co = i / 112, rem = i - co*112;
            int ci = rem / 7, kh = rem - ci*7;
            float v = w[((size_t)(co0+co)*CP + cc+ci)*7 + kh];
            swp[(co*16 + ci)*7 + kh] = pack2(v, v);
        }
        __syncthreads();
        #pragma unroll
        for (int ci = 0; ci < 16; ci++) {
            ull iv[10];
            #pragma unroll
            for (int r = 0; r < 10; r++)
                iv[r] = *(const ull*)&sin[(ci*14 + yh*4 + r)*32 + 2*xp];
            #pragma unroll
            for (int kh = 0; kh < 7; kh++) {
                #pragma unroll
                for (int j = 0; j < 8; j++) {
                    ull wv2 = swp[((cg*8 + j)*16 + ci)*7 + kh];
                    #pragma unroll
                    for (int k = 0; k < 4; k++) ffma2(acc[j][k], wv2, iv[k + kh]);
                }
            }
        }
        __syncthreads();
    }
    #pragma unroll
    for (int j = 0; j < 8; j++) {
        int co = co0 + cg*8 + j;
        float s = 0.f, s2 = 0.f;
        #pragma unroll
        for (int k = 0; k < 4; k++) {
            float v0, v1; unpack2(acc[j][k], v0, v1);
            *(float2*)&out[(((size_t)b*CP + co)*HH + y0 + yh*4 + k)*WW + 2*xp] = make_float2(v0, v1);
            s += v0 + v1; s2 += v0*v0 + v1*v1;
        }
        #pragma unroll
        for (int o = 16; o > 0; o >>= 1) {
            s  += __shfl_xor_sync(0xffffffffu, s,  o);
            s2 += __shfl_xor_sync(0xffffffffu, s2, o);
        }
        if ((tid & 31) == 0 && oslot >= 0) {
            atomicAdd(&g_ssum [oslot*CP + co], (double)s);
            atomicAdd(&g_ssum2[oslot*CP + co], (double)s2);
        }
    }
}

// ---------------- final combine + scatter (float4) ----------------------------
__global__ void combine_kernel(const float* __restrict__ wv, float* __restrict__ out) {
    int n4 = blockIdx.x * 256 + threadIdx.x;   // < NSEL/4
    int n = n4 << 2;
    int b = n >> 17, p = (n >> 10) & 127, hw = n & 1023;
    float m0 = g_meanv[0*CP+p],  r0 = g_rstdv[0*CP+p];
    float m1 = g_meanv[1*CP+p],  r1 = g_rstdv[1*CP+p];
    float m3 = g_meanv[3*CP+p],  r3 = g_rstdv[3*CP+p];
    float m5 = g_meanv[5*CP+p],  r5 = g_rstdv[5*CP+p];
    float m7 = g_meanv[7*CP+p],  r7 = g_rstdv[7*CP+p];
    float m8 = g_meanv[8*CP+p],  r8 = g_rstdv[8*CP+p];
    float m9 = g_meanv[9*CP+p],  r9 = g_rstdv[9*CP+p];
    float mA = g_meanv[10*CP+p], rA = g_rstdv[10*CP+p];
    float w1=wv[1],w2=wv[2],w3=wv[3],w4=wv[4],w5=wv[5],w6=wv[6],w7=wv[7],w8=wv[8],w9=wv[9];
    float a[4] = {0.f,0.f,0.f,0.f};
    { float4 v = *(const float4*)&g_bmax[n];  const float* q=(const float*)&v;
      #pragma unroll
      for (int t=0;t<4;t++) a[t] += w1*(q[t]-m0)*r0; }
    { float4 v = *(const float4*)&g_bavg[n];  const float* q=(const float*)&v;
      #pragma unroll
      for (int t=0;t<4;t++) a[t] += w2*(q[t]-m1)*r1; }
    { float4 v = *(const float4*)&g_xtemp[n]; const float* q=(const float*)&v;
      #pragma unroll
      for (int t=0;t<4;t++) a[t] += w3*q[t]; }
    { float4 v = *(const float4*)&g_s3[n];    const float* q=(const float*)&v;
      #pragma unroll
      for (int t=0;t<4;t++) a[t] += w4*(q[t]-m3)*r3; }
    { float4 v = *(const float4*)&g_s5[n];    const float* q=(const float*)&v;
      #pragma unroll
      for (int t=0;t<4;t++) a[t] += w5*(q[t]-m5)*r5; }
    { float4 v = *(const float4*)&g_s7[n];    const float* q=(const float*)&v;
      #pragma unroll
      for (int t=0;t<4;t++) a[t] += w6*(q[t]-m7)*r7; }
    { float4 v = *(const float4*)&g_d3[n];    const float* q=(const float*)&v;
      #pragma unroll
      for (int t=0;t<4;t++) a[t] += w7*(q[t]-m8)*r8; }
    { float4 v = *(const float4*)&g_d5[n];    const float* q=(const float*)&v;
      #pragma unroll
      for (int t=0;t<4;t++) a[t] += w8*(q[t]-m9)*r9; }
    { float4 v = *(const float4*)&g_c7[n];    const float* q=(const float*)&v;
      #pragma unroll
      for (int t=0;t<4;t++) a[t] += w9*(q[t]-mA)*rA; }
    int cs = g_idx[p];
    *(float4*)&out[(((size_t)b*C + cs) << 10) + hw] = make_float4(a[0],a[1],a[2],a[3]);
}

// =============================================================================
extern "C" void kernel_launch(void* const* d_in, const int* in_sizes, int n_in,
                              void* d_out, int out_size) {
    const float* x        = (const float*)d_in[0];
    const float* weights  = (const float*)d_in[1];
    const float* wall     = (const float*)d_in[2];
    const float* w_fc1    = (const float*)d_in[3];
    const float* w_fc2    = (const float*)d_in[4];
    const float* sep3_dw1 = (const float*)d_in[5];
    const float* sep3_pw1 = (const float*)d_in[6];
    const float* sep3_dw2 = (const float*)d_in[7];
    const float* sep3_pw2 = (const float*)d_in[8];
    const float* sep5_dw1 = (const float*)d_in[9];
    const float* sep5_pw1 = (const float*)d_in[10];
    const float* sep5_dw2 = (const float*)d_in[11];
    const float* sep5_pw2 = (const float*)d_in[12];
    const float* sep7_dw1 = (const float*)d_in[13];
    const float* sep7_pw1 = (const float*)d_in[14];
    const float* sep7_dw2 = (const float*)d_in[15];
    const float* sep7_pw2 = (const float*)d_in[16];
    const float* dil3_dw  = (const float*)d_in[17];
    const float* dil3_pw  = (const float*)d_in[18];
    const float* dil5_dw  = (const float*)d_in[19];
    const float* dil5_pw  = (const float*)d_in[20];
    const float* w_1x7    = (const float*)d_in[21];
    const float* w_7x1    = (const float*)d_in[22];
    float* out = (float*)d_out;

    // Resolve REAL device addresses (host shadow symbols are ATS garbage on GB300).
    float *t_xtemp,*t_1,*t_2,*t_bmax,*t_bavg,*t_s3,*t_s5,*t_s7,*t_d3,*t_d5,*t_c7;
    { void* p;
      cudaGetSymbolAddress(&p, g_xtemp); t_xtemp=(float*)p;
      cudaGetSymbolAddress(&p, g_t1);    t_1    =(float*)p;
      cudaGetSymbolAddress(&p, g_t2);    t_2    =(float*)p;
      cudaGetSymbolAddress(&p, g_bmax);  t_bmax =(float*)p;
      cudaGetSymbolAddress(&p, g_bavg);  t_bavg =(float*)p;
      cudaGetSymbolAddress(&p, g_s3);    t_s3   =(float*)p;
      cudaGetSymbolAddress(&p, g_s5);    t_s5   =(float*)p;
      cudaGetSymbolAddress(&p, g_s7);    t_s7   =(float*)p;
      cudaGetSymbolAddress(&p, g_d3);    t_d3   =(float*)p;
      cudaGetSymbolAddress(&p, g_d5);    t_d5   =(float*)p;
      cudaGetSymbolAddress(&p, g_c7);    t_c7   =(float*)p; }

    const int SM1X7  = (16*8*40*2)*4 + 64*16*7*8;   // 96 KB
    const int SM7X1  = (16*14*32)*4 + 64*16*7*8;    // 84 KB
    const int SMPW   = 106496;                      // W hi/lo + X hi/lo bf16 tiles
    cudaFuncSetAttribute(conv1x7_kernel, cudaFuncAttributeMaxDynamicSharedMemorySize, SM1X7);
    cudaFuncSetAttribute(conv7x1_kernel, cudaFuncAttributeMaxDynamicSharedMemorySize, SM7X1);
    cudaFuncSetAttribute(pw_mma_kernel,  cudaFuncAttributeMaxDynamicSharedMemorySize, SMPW);

    const int GSEL4 = NSEL / 1024;   // 8192
    const int GALL4 = NALL / 1024;   // 32768
    dim3 gcv(2, 4, B);               // 64co x 8y tiles (7-convs)
    dim3 gpw(16, B);                 // pw MMA: 16 spatial tiles x 64 batches
    const int GDW = B * CP;          // 8192

    // prefix (launch index 3 = first pw_mma -> gets ncu-sampled)
    attn_fused_kernel<<<B, 512>>>(x, w_fc1, wall, w_fc2);
    slist_topk_kernel<<<1, C>>>();

    // sep3 (dw gathers from x directly)
    dw_conv_kernel<3,1,1,1><<<GDW, 256>>>(x, t_1, sep3_dw1, 0);
    pw_mma_kernel<<<gpw, 256, SMPW>>>(t_1, t_2, sep3_pw1, 2);     // <- PROFILED
    dw_conv_kernel<3,1,2,0><<<GDW, 256>>>(t_2, t_1, sep3_dw2, 2);
    pw_mma_kernel<<<gpw, 256, SMPW>>>(t_1, t_s3, sep3_pw2, 3);

    // sep5
    dw_conv_kernel<5,1,1,1><<<GDW, 256>>>(x, t_1, sep5_dw1, 0);
    pw_mma_kernel<<<gpw, 256, SMPW>>>(t_1, t_2, sep5_pw1, 4);
    dw_conv_kernel<5,1,2,0><<<GDW, 256>>>(t_2, t_1, sep5_dw2, 4);
    pw_mma_kernel<<<gpw, 256, SMPW>>>(t_1, t_s5, sep5_pw2, 5);

    // sep7
    dw_conv_kernel<7,1,1,1><<<GDW, 256>>>(x, t_1, sep7_dw1, 0);
    pw_mma_kernel<<<gpw, 256, SMPW>>>(t_1, t_2, sep7_pw1, 6);
    dw_conv_kernel<7,1,2,0><<<GDW, 256>>>(t_2, t_1, sep7_dw2, 6);
    pw_mma_kernel<<<gpw, 256, SMPW>>>(t_1, t_s7, sep7_pw2, 7);

    // dilated
    dw_conv_kernel<3,2,1,1><<<GDW, 256>>>(x, t_1, dil3_dw, 0);
    pw_mma_kernel<<<gpw, 256, SMPW>>>(t_1, t_d3, dil3_pw, 8);
    dw_conv_kernel<5,2,1,1><<<GDW, 256>>>(x, t_1, dil5_dw, 0);
    pw_mma_kernel<<<gpw, 256, SMPW>>>(t_1, t_d5, dil5_pw, 9);

    // 1x7 (gathers from x) -> 7x1 (slot 10)
    conv1x7_kernel<<<gcv, 256, SM1X7>>>(x, t_1, w_1x7);
    conv7x1_kernel<<<gcv, 256, SM7X1>>>(t_1, t_c7, w_7x1, 10);

    // independent passes
    gather4_kernel<<<GSEL4, 256>>>(x);
    scale4_kernel<<<GALL4, 256>>>(x, out);
    pool3f_kernel<<<GDW, 256>>>(x, t_bmax, t_bavg);

    // finalize all stats, combine, scatter
    finalize_kernel<<<NSLOT, 128>>>();
    combine_kernel<<<GSEL4, 256>>>(weights, out);
}

// round 17
// speedup vs baseline: 1.8054x; 1.3577x over previous
#include <cuda_runtime.h>
#include <cuda_bf16.h>
#include <math.h>
#include <stdint.h>

#define B   64
#define C   512
#define CP  128
#define HH  32
#define WW  32
#define HW  1024
#define NSEL (B*CP*HW)       // 8388608
#define NALL (B*C*HW)        // 33554432
#define NSLOT 11

// ---------------- scratch (device globals; no allocs allowed) ----------------
__device__ float g_ca[B*C];
__device__ int   g_idx[CP];
__device__ float g_xtemp[NSEL];
__device__ float g_t1[NSEL];
__device__ float g_t2[NSEL];
__device__ float g_bmax[NSEL];
__device__ float g_bavg[NSEL];
__device__ float g_s3[NSEL];
__device__ float g_s5[NSEL];
__device__ float g_s7[NSEL];
__device__ float g_d3[NSEL];
__device__ float g_d5[NSEL];
__device__ float g_c7[NSEL];
__device__ float g_w17t[7*CP*CP];   // W(1x7) transposed to [kw][co][ci]
__device__ float g_w71t[7*CP*CP];   // W(7x1) transposed to [kh][co][ci]
__device__ double g_ssum [NSLOT*CP];
__device__ double g_ssum2[NSLOT*CP];
__device__ float  g_meanv[NSLOT*CP];
__device__ float  g_rstdv[NSLOT*CP];

// slots: 0 max, 1 avg, 2 sep3mid, 3 sep3fin, 4 sep5mid, 5 sep5fin,
//        6 sep7mid, 7 sep7fin, 8 dil3, 9 dil5, 10 c7

typedef unsigned long long ull;
__device__ __forceinline__ uint32_t smem_u32(const void* p){
    uint32_t a;
    asm("{ .reg .u64 t; cvta.to.shared.u64 t, %1; cvt.u32.u64 %0, t; }":"=r"(a):"l"(p));
    return a;
}
// ---- mma.sync helpers (sm_80 PTX; legal on compute_103, unlike tcgen05) -----
__device__ __forceinline__ void ldsm_x4(uint32_t&a0,uint32_t&a1,uint32_t&a2,uint32_t&a3,uint32_t addr){
    asm volatile("ldmatrix.sync.aligned.m8n8.x4.shared.b16 {%0,%1,%2,%3},[%4];"
        :"=r"(a0),"=r"(a1),"=r"(a2),"=r"(a3):"r"(addr));
}
__device__ __forceinline__ void ldsm_x2t(uint32_t&b0,uint32_t&b1,uint32_t addr){
    asm volatile("ldmatrix.sync.aligned.m8n8.x2.trans.shared.b16 {%0,%1},[%2];"
        :"=r"(b0),"=r"(b1):"r"(addr));
}
__device__ __forceinline__ void ldsm_x2(uint32_t&b0,uint32_t&b1,uint32_t addr){
    asm volatile("ldmatrix.sync.aligned.m8n8.x2.shared.b16 {%0,%1},[%2];"
        :"=r"(b0),"=r"(b1):"r"(addr));
}
__device__ __forceinline__ void mma_bf16(float&d0,float&d1,float&d2,float&d3,
                                         uint32_t a0,uint32_t a1,uint32_t a2,uint32_t a3,
                                         uint32_t b0,uint32_t b1){
    asm volatile("mma.sync.aligned.m16n8k16.row.col.f32.bf16.bf16.f32 "
        "{%0,%1,%2,%3},{%4,%5,%6,%7},{%8,%9},{%0,%1,%2,%3};"
        :"+f"(d0),"+f"(d1),"+f"(d2),"+f"(d3)
        :"r"(a0),"r"(a1),"r"(a2),"r"(a3),"r"(b0),"r"(b1));
}
__device__ __forceinline__ void bf16_split(float v, __nv_bfloat16&h, __nv_bfloat16&l){
    h = __float2bfloat16(v);
    l = __float2bfloat16(v - __bfloat162float(h));
}

// ---------------- 0. fused global pooling + attention MLP (+ stats zero) -----
__global__ void __launch_bounds__(512) attn_fused_kernel(
        const float* __restrict__ x, const float* __restrict__ fc1,
        const float* __restrict__ wa, const float* __restrict__ fc2) {
    int b = blockIdx.x, tid = threadIdx.x;     // 512 threads
    __shared__ float pooled[1024];
    __shared__ float red[16];
    __shared__ float s_y[10], s_A[100], s_y2[10];
    if (b == 0) {
        for (int i = tid; i < NSLOT*CP; i += 512) { g_ssum[i] = 0.0; g_ssum2[i] = 0.0; }
    }
    int w = tid >> 5, l = tid & 31;
    for (int j = 0; j < 32; j++) {
        int c = w*32 + j;
        const float* p = x + ((size_t)(b*C + c) << 10);
        float s = 0.f, m = -INFINITY;
        #pragma unroll 4
        for (int k = 0; k < 32; k++) { float v = p[l + 32*k]; s += v; m = fmaxf(m, v); }
        #pragma unroll
        for (int o = 16; o > 0; o >>= 1) {
            s += __shfl_xor_sync(0xffffffffu, s, o);
            m = fmaxf(m, __shfl_xor_sync(0xffffffffu, m, o));
        }
        if (l == 0) { pooled[c] = s * (1.f/1024.f); pooled[C + c] = m; }
    }
    __syncthreads();
    for (int j = 0; j < 10; j++) {
        float local = pooled[tid] * fc1[j*2*C + tid] + pooled[512 + tid] * fc1[j*2*C + 512 + tid];
        #pragma unroll
        for (int o = 16; o > 0; o >>= 1) local += __shfl_xor_sync(0xffffffffu, local, o);
        if (l == 0) red[w] = local;
        __syncthreads();
        if (tid == 0) { float t = 0.f; for (int q = 0; q < 16; q++) t += red[q]; s_y[j] = t; }
        __syncthreads();
    }
    if (tid < 100) {
        int j = tid / 10, k = tid % 10;
        float a = 0.f;
        for (int m = 0; m < 14; m++) a += wa[m*10 + j] * wa[m*10 + k];
        s_A[tid] = a;
    }
    __syncthreads();
    if (tid < 10) {
        float v = 0.f;
        for (int k = 0; k < 10; k++) v += s_y[k] * s_A[tid*10 + k];
        s_y2[tid] = fmaxf(v, 0.f);
    }
    __syncthreads();
    {
        int c = tid;
        float v = 0.f;
        for (int j = 0; j < 10; j++) v += s_y2[j] * fc2[c*10 + j];
        g_ca[b*C + c] = 1.f / (1.f + expf(-v));
    }
}

// ---------------- 1. slist + exact lax.top_k ordering (merged) ----------------
__global__ void slist_topk_kernel() {
    __shared__ float v[C];
    int c = threadIdx.x;                       // 512
    float s = 0.f;
    for (int b = 0; b < B; b++) s += g_ca[b*C + c];
    v[c] = s; __syncthreads();
    float mv = v[c];
    int rank = 0;
    for (int i = 0; i < C; i++) {
        float o = v[i];
        rank += (o > mv) || (o == mv && i < c);
    }
    if (rank < CP) g_idx[rank] = c;
}

// ---------------- W transpose: [co][ci][k7] -> [k][co][ci] -------------------
__global__ void transw_kernel(const float* __restrict__ w17, const float* __restrict__ w71) {
    int i = blockIdx.x * 256 + threadIdx.x;    // < 114688
    if (i < 7*CP*CP) {
        int kh = i >> 14, rem = i & 16383;     // rem = co*128+ci
        g_w17t[i] = w17[rem*7 + kh];
        g_w71t[i] = w71[rem*7 + kh];
    }
}

// ---------------- gather xtemp (for identity branch in combine) --------------
__global__ void gather4_kernel(const float* __restrict__ x) {
    int n4 = blockIdx.x * 256 + threadIdx.x;   // < NSEL/4
    int n = n4 << 2;
    int b = n >> 17, p = (n >> 10) & 127, hw = n & 1023;
    int cs = g_idx[p];
    float ca = g_ca[b*C + cs];
    float4 v = *(const float4*)&x[(((size_t)b*C + cs) << 10) + hw];
    v.x *= ca; v.y *= ca; v.z *= ca; v.w *= ca;
    *(float4*)&g_xtemp[n] = v;
}

// ---------------- scale x by ca into d_out (float4) ----------------
__global__ void scale4_kernel(const float* __restrict__ x, float* __restrict__ out) {
    int n4 = blockIdx.x * 256 + threadIdx.x;   // < NALL/4
    int n = n4 << 2;
    float ca = g_ca[n >> 10];
    float4 v = *(const float4*)&x[n];
    v.x *= ca; v.y *= ca; v.z *= ca; v.w *= ca;
    *(float4*)&out[n] = v;
}

// ---------------- fused 3x3 max+avg pool + stats (gathers from x) ------------
__global__ void __launch_bounds__(256) pool3f_kernel(const float* __restrict__ x,
                                                     float* __restrict__ omax,
                                                     float* __restrict__ oavg) {
    __shared__ float s[34][35];
    __shared__ float rsm[8][4];
    int bc = blockIdx.x;
    int tid = threadIdx.x;
    int b = bc >> 7, p = bc & 127;
    int cs = g_idx[p];
    float ca = g_ca[b*C + cs];
    const float* ip = x + ((size_t)(b*C + cs) << 10);
    for (int i = tid; i < 34*34; i += 256) {
        int r = i / 34, q = i - r*34;
        int y = r - 1, xx = q - 1;
        s[r][q] = (y >= 0 && y < 32 && xx >= 0 && xx < 32) ? ip[y*32 + xx] * ca : 0.f;
    }
    __syncthreads();
    int y = tid >> 3, x0 = (tid & 7) * 4;
    float vmax[4], vavg[4];
    int yl = (y > 0 ? y-1 : 0), yhh = (y < 31 ? y+1 : 31);
    int ch = yhh - yl + 1;
    #pragma unroll
    for (int t = 0; t < 4; t++) {
        int xx = x0 + t;
        float m = -INFINITY, sm = 0.f;
        #pragma unroll
        for (int dy = 0; dy < 3; dy++) {
            int yy = y + dy;
            bool yok = (yy >= 1 && yy <= 32);
            #pragma unroll
            for (int dx = 0; dx < 3; dx++) {
                int xq = xx + dx;
                float v = s[yy][xq];
                sm += v;
                if (yok && xq >= 1 && xq <= 32) m = fmaxf(m, v);
            }
        }
        int xl = (xx > 0 ? xx-1 : 0), xh = (xx < 31 ? xx+1 : 31);
        int cnt = ch * (xh - xl + 1);
        vmax[t] = m; vavg[t] = sm / (float)cnt;
    }
    size_t base = ((size_t)bc << 10) + y*32 + x0;
    *(float4*)&omax[base] = make_float4(vmax[0],vmax[1],vmax[2],vmax[3]);
    *(float4*)&oavg[base] = make_float4(vavg[0],vavg[1],vavg[2],vavg[3]);
    float sM=0,sM2=0,sA=0,sA2=0;
    #pragma unroll
    for (int t = 0; t < 4; t++) { sM += vmax[t]; sM2 += vmax[t]*vmax[t]; sA += vavg[t]; sA2 += vavg[t]*vavg[t]; }
    #pragma unroll
    for (int o = 16; o > 0; o >>= 1) {
        sM  += __shfl_xor_sync(0xffffffffu, sM,  o);
        sM2 += __shfl_xor_sync(0xffffffffu, sM2, o);
        sA  += __shfl_xor_sync(0xffffffffu, sA,  o);
        sA2 += __shfl_xor_sync(0xffffffffu, sA2, o);
    }
    int w = tid >> 5;
    if ((tid & 31) == 0) { rsm[w][0]=sM; rsm[w][1]=sM2; rsm[w][2]=sA; rsm[w][3]=sA2; }
    __syncthreads();
    if (tid == 0) {
        float a=0,b2=0,c2=0,d2=0;
        for (int q = 0; q < 8; q++) { a+=rsm[q][0]; b2+=rsm[q][1]; c2+=rsm[q][2]; d2+=rsm[q][3]; }
        atomicAdd(&g_ssum [0*CP + p], (double)a);
        atomicAdd(&g_ssum2[0*CP + p], (double)b2);
        atomicAdd(&g_ssum [1*CP + p], (double)c2);
        atomicAdd(&g_ssum2[1*CP + p], (double)d2);
    }
}

// ---------------- finalize stats ----------------
__global__ void finalize_kernel() {
    int s = blockIdx.x, c = threadIdx.x;       // 11 x 128
    double su = g_ssum[s*CP+c], sq = g_ssum2[s*CP+c];
    double m  = su * (1.0/65536.0);
    double var = sq * (1.0/65536.0) - m*m;
    g_meanv[s*CP+c] = (float)m;
    g_rstdv[s*CP+c] = (float)rsqrt(var + 1e-5);
}

// ------- depthwise conv; TRANS: 1 relu, 2 bn+relu; GATHER: read x via idx ----
template<int K, int DIL, int TRANS, int GATHER>
__global__ void __launch_bounds__(256) dw_conv_kernel(const float* __restrict__ in,
                                                      float* __restrict__ out,
                                                      const float* __restrict__ w,
                                                      int islot) {
    constexpr int P  = (DIL==1) ? (K/2) : (K-1);
    constexpr int SW = 32 + 2*P;
    constexpr int SWP = SW + 1;
    constexpr int SPAN = 4 + (K-1)*DIL;
    __shared__ float s[SW][SWP];
    __shared__ float s_mr[2];
    int bc = blockIdx.x;
    int b = bc >> 7, c = bc & 127;
    int tid = threadIdx.x;
    if (TRANS == 2 && tid == 0) {
        double su = g_ssum[islot*CP + c], sq = g_ssum2[islot*CP + c];
        double m = su * (1.0/65536.0);
        double var = sq * (1.0/65536.0) - m*m;
        s_mr[0] = (float)m; s_mr[1] = (float)rsqrt(var + 1e-5);
    }
    if (TRANS == 2) __syncthreads();
    float mean = 0.f, rstd = 1.f;
    if (TRANS == 2) { mean = s_mr[0]; rstd = s_mr[1]; }
    const float* ip;
    float ca = 1.f;
    if (GATHER) {
        int cs = g_idx[c];
        ca = g_ca[b*C + cs];
        ip = in + ((size_t)(b*C + cs) << 10);
    } else {
        ip = in + ((size_t)bc << 10);
    }
    for (int i = tid; i < SW*SW; i += 256) {
        int r = i / SW, q = i - r*SW;
        int y = r - P, xx = q - P;
        float v = 0.f;
        if (y >= 0 && y < 32 && xx >= 0 && xx < 32) {
            v = ip[y*32 + xx];
            if (GATHER) v *= ca;
            if (TRANS == 1) v = fmaxf(v, 0.f);
            else if (TRANS == 2) v = fmaxf((v - mean)*rstd, 0.f);
        }
        s[r][q] = v;
    }
    float wr[K][K];
    #pragma unroll
    for (int i = 0; i < K; i++)
        #pragma unroll
        for (int j = 0; j < K; j++) wr[i][j] = w[(c*K + i)*K + j];
    __syncthreads();
    int y = tid >> 3, x0 = (tid & 7) * 4;
    float acc[4] = {0.f, 0.f, 0.f, 0.f};
    #pragma unroll
    for (int i = 0; i < K; i++) {
        float r[SPAN];
        #pragma unroll
        for (int q = 0; q < SPAN; q++) r[q] = s[y + i*DIL][x0 + q];
        #pragma unroll
        for (int j = 0; j < K; j++)
            #pragma unroll
            for (int t = 0; t < 4; t++) acc[t] = fmaf(wr[i][j], r[j*DIL + t], acc[t]);
    }
    *(float4*)&out[((size_t)bc << 10) + y*32 + x0] = make_float4(acc[0],acc[1],acc[2],acc[3]);
}

// -------- pointwise conv 128->128 via mma.sync bf16-split (3 passes) ---------
// Block = (b, 64 spatial) tile; grid (16, B). 256 thr = 8 warps; warp owns 16 co.
__global__ void __launch_bounds__(256, 2) pw_mma_kernel(const float* __restrict__ in,
                                                        float* __restrict__ out,
                                                        const float* __restrict__ w,
                                                        int oslot) {
    extern __shared__ __align__(16) char dsm[];
    const uint32_t oWlo = 34816u, oXhi = 69632u, oXlo = 88064u;
    int tid = threadIdx.x, lane = tid & 31, wid = tid >> 5;
    int tile = blockIdx.x;          // 0..15 -> spatial base tile*64
    int b = blockIdx.y;
    int sp0 = tile * 64;
    uint32_t sbase = smem_u32(dsm);

    // fill W hi/lo
    #pragma unroll
    for (int t = 0; t < 16; t++) {
        int idx4 = tid + t*256;                 // 0..4095
        int co = idx4 >> 5, c0 = (idx4 & 31) << 2;
        float4 v = *(const float4*)&w[(co << 7) + c0];
        __nv_bfloat16 h0,h1,h2,h3,l0,l1,l2,l3;
        bf16_split(v.x,h0,l0); bf16_split(v.y,h1,l1);
        bf16_split(v.z,h2,l2); bf16_split(v.w,h3,l3);
        uint32_t off = (uint32_t)co*272u + (uint32_t)c0*2u;
        *(uint32_t*)(dsm + off)        = ((uint32_t)__bfloat16_as_ushort(h1)<<16) | __bfloat16_as_ushort(h0);
        *(uint32_t*)(dsm + off + 4)    = ((uint32_t)__bfloat16_as_ushort(h3)<<16) | __bfloat16_as_ushort(h2);
        *(uint32_t*)(dsm + oWlo + off)     = ((uint32_t)__bfloat16_as_ushort(l1)<<16) | __bfloat16_as_ushort(l0);
        *(uint32_t*)(dsm + oWlo + off + 4) = ((uint32_t)__bfloat16_as_ushort(l3)<<16) | __bfloat16_as_ushort(l2);
    }
    // fill X hi/lo  (k-major rows: X[ci][n], 72-elem rows)
    #pragma unroll
    for (int t = 0; t < 8; t++) {
        int idx4 = tid + t*256;                 // 0..2047
        int ci = idx4 >> 4, n0 = (idx4 & 15) << 2;
        float4 v = *(const float4*)&in[(((size_t)b*CP + ci) << 10) + sp0 + n0];
        __nv_bfloat16 h0,h1,h2,h3,l0,l1,l2,l3;
        bf16_split(v.x,h0,l0); bf16_split(v.y,h1,l1);
        bf16_split(v.z,h2,l2); bf16_split(v.w,h3,l3);
        uint32_t off = (uint32_t)ci*144u + (uint32_t)n0*2u;
        *(uint32_t*)(dsm + oXhi + off)     = ((uint32_t)__bfloat16_as_ushort(h1)<<16) | __bfloat16_as_ushort(h0);
        *(uint32_t*)(dsm + oXhi + off + 4) = ((uint32_t)__bfloat16_as_ushort(h3)<<16) | __bfloat16_as_ushort(h2);
        *(uint32_t*)(dsm + oXlo + off)     = ((uint32_t)__bfloat16_as_ushort(l1)<<16) | __bfloat16_as_ushort(l0);
        *(uint32_t*)(dsm + oXlo + off + 4) = ((uint32_t)__bfloat16_as_ushort(l3)<<16) | __bfloat16_as_ushort(l2);
    }
    __syncthreads();

    float acc[8][4];
    #pragma unroll
    for (int nt = 0; nt < 8; nt++)
        #pragma unroll
        for (int q = 0; q < 4; q++) acc[nt][q] = 0.f;

    uint32_t arow = (uint32_t)(wid*16 + (lane & 15));
    uint32_t ahalf = (uint32_t)(lane >> 4);
    uint32_t bro = (uint32_t)(lane & 15) * 144u;

    #pragma unroll
    for (int pass = 0; pass < 3; pass++) {
        uint32_t aaddr = sbase + (pass == 2 ? oWlo : 0u) + arow*272u + ahalf*16u;
        uint32_t bbase = sbase + (pass == 1 ? oXlo : oXhi) + bro;
        #pragma unroll
        for (int k = 0; k < 8; k++) {
            uint32_t a0,a1,a2,a3;
            ldsm_x4(a0,a1,a2,a3, aaddr + (uint32_t)k*32u);
            uint32_t brow = bbase + (uint32_t)k*2304u;   // 16 rows * 144B
            #pragma unroll
            for (int nt = 0; nt < 8; nt++) {
                uint32_t b0,b1;
                ldsm_x2t(b0,b1, brow + (uint32_t)nt*16u);
                mma_bf16(acc[nt][0],acc[nt][1],acc[nt][2],acc[nt][3], a0,a1,a2,a3, b0,b1);
            }
        }
    }

    // epilogue: write D + fused per-channel stats
    int coA = wid*16 + (lane >> 2);
    int coB = coA + 8;
    float sA=0.f, sA2=0.f, sB=0.f, sB2=0.f;
    #pragma unroll
    for (int nt = 0; nt < 8; nt++) {
        int sp = sp0 + nt*8 + (lane & 3)*2;
        *(float2*)&out[(((size_t)b*CP + coA) << 10) + sp] = make_float2(acc[nt][0], acc[nt][1]);
        *(float2*)&out[(((size_t)b*CP + coB) << 10) + sp] = make_float2(acc[nt][2], acc[nt][3]);
        sA += acc[nt][0] + acc[nt][1]; sA2 += acc[nt][0]*acc[nt][0] + acc[nt][1]*acc[nt][1];
        sB += acc[nt][2] + acc[nt][3]; sB2 += acc[nt][2]*acc[nt][2] + acc[nt][3]*acc[nt][3];
    }
    #pragma unroll
    for (int o = 1; o < 4; o <<= 1) {
        sA  += __shfl_xor_sync(0xffffffffu, sA,  o);
        sA2 += __shfl_xor_sync(0xffffffffu, sA2, o);
        sB  += __shfl_xor_sync(0xffffffffu, sB,  o);
        sB2 += __shfl_xor_sync(0xffffffffu, sB2, o);
    }
    if ((lane & 3) == 0 && oslot >= 0) {
        atomicAdd(&g_ssum [oslot*CP + coA], (double)sA);
        atomicAdd(&g_ssum2[oslot*CP + coA], (double)sA2);
        atomicAdd(&g_ssum [oslot*CP + coB], (double)sB);
        atomicAdd(&g_ssum2[oslot*CP + coB], (double)sB2);
    }
}

// ------- 1x7 conv via mma.sync: 7 shifted GEMM passes, Xt n-major layout -----
// Block = (b, 2 y-rows = 64 n); grid (16, B). relu(gather(x)) input.
// Xt[76 rows = 2y x 38x-halo][128 ci] hi/lo (272B rows); Wk[128co][128ci] hi/lo
// staged per kw from g_w17t. B-frag = NON-trans ldmatrix on n-major rows
// (row shift = x shift, always 16B-aligned).
__global__ void __launch_bounds__(256, 2) c1x7_mma_kernel(const float* __restrict__ x,
                                                          float* __restrict__ out) {
    extern __shared__ __align__(16) char dsm[];
    const uint32_t oXlo = 20672u, oWhi = 41344u, oWlo = 76160u;  // total 110976
    int tid = threadIdx.x, lane = tid & 31, wid = tid >> 5;
    int tile = blockIdx.x, b = blockIdx.y;
    int y0 = tile * 2;
    uint32_t sbase = smem_u32(dsm);

    // fill Xt hi/lo: 76 rows x 128 ci; row r = yy*38 + (xx+3)
    for (int i = tid; i < 9728; i += 256) {
        int ci = i / 76, r = i - ci*76;
        int yy = (r >= 38) ? 1 : 0;
        int xx = r - yy*38 - 3;
        float v = 0.f;
        if (xx >= 0 && xx < 32) {
            int cs = g_idx[ci];
            v = fmaxf(x[(((size_t)b*C + cs)*HH + y0+yy)*WW + xx] * g_ca[b*C + cs], 0.f);
        }
        __nv_bfloat16 h, l; bf16_split(v, h, l);
        uint32_t off = (uint32_t)r*272u + (uint32_t)ci*2u;
        *(__nv_bfloat16*)(dsm + off) = h;
        *(__nv_bfloat16*)(dsm + oXlo + off) = l;
    }

    float acc[8][4];
    #pragma unroll
    for (int nt = 0; nt < 8; nt++)
        #pragma unroll
        for (int q = 0; q < 4; q++) acc[nt][q] = 0.f;

    uint32_t arowoff = (uint32_t)(wid*16 + (lane & 15))*272u + (uint32_t)(lane >> 4)*16u;
    uint32_t l8 = (uint32_t)(lane & 7);
    uint32_t bhalf = (uint32_t)((lane >> 3) & 1) * 16u;

    for (int kw = 0; kw < 7; kw++) {
        __syncthreads();                       // X fill / previous mma done
        // stage Wk hi/lo from g_w17t[kw][co][ci]
        const float* wsrc = g_w17t + kw*16384;
        for (int i = tid; i < 4096; i += 256) {  // float4 units
            int co = i >> 5, c0 = (i & 31) << 2;
            float4 v = *(const float4*)&wsrc[(co << 7) + c0];
            __nv_bfloat16 h0,h1,h2,h3,l0,l1,l2,l3;
            bf16_split(v.x,h0,l0); bf16_split(v.y,h1,l1);
            bf16_split(v.z,h2,l2); bf16_split(v.w,h3,l3);
            uint32_t off = (uint32_t)co*272u + (uint32_t)c0*2u;
            *(uint32_t*)(dsm + oWhi + off)     = ((uint32_t)__bfloat16_as_ushort(h1)<<16) | __bfloat16_as_ushort(h0);
            *(uint32_t*)(dsm + oWhi + off + 4) = ((uint32_t)__bfloat16_as_ushort(h3)<<16) | __bfloat16_as_ushort(h2);
            *(uint32_t*)(dsm + oWlo + off)     = ((uint32_t)__bfloat16_as_ushort(l1)<<16) | __bfloat16_as_ushort(l0);
            *(uint32_t*)(dsm + oWlo + off + 4) = ((uint32_t)__bfloat16_as_ushort(l3)<<16) | __bfloat16_as_ushort(l2);
        }
        __syncthreads();
        #pragma unroll
        for (int pass = 0; pass < 3; pass++) {
            uint32_t aaddr = sbase + (pass == 2 ? oWlo : oWhi) + arowoff;
            uint32_t xoff  = (pass == 1) ? oXlo : 0u;
            #pragma unroll
            for (int kc = 0; kc < 8; kc++) {
                uint32_t a0,a1,a2,a3;
                ldsm_x4(a0,a1,a2,a3, aaddr + (uint32_t)kc*32u);
                #pragma unroll
                for (int nt = 0; nt < 8; nt++) {
                    // row = n + kw + (n>=32)*6, with n = nt*8 + l8
                    uint32_t row = (uint32_t)(nt*8) + l8 + (uint32_t)kw + (uint32_t)((nt >> 2) * 6);
                    uint32_t b0,b1;
                    ldsm_x2(b0,b1, sbase + xoff + row*272u + (uint32_t)kc*32u + bhalf);
                    mma_bf16(acc[nt][0],acc[nt][1],acc[nt][2],acc[nt][3], a0,a1,a2,a3, b0,b1);
                }
            }
        }
    }

    int coA = wid*16 + (lane >> 2);
    int coB = coA + 8;
    #pragma unroll
    for (int nt = 0; nt < 8; nt++) {
        int n = nt*8 + (lane & 3)*2;
        int yy = n >> 5, xx = n & 31;
        size_t o = (((size_t)b*CP + coA)*HH + y0+yy)*WW + xx;
        *(float2*)&out[o] = make_float2(acc[nt][0], acc[nt][1]);
        size_t o2 = (((size_t)b*CP + coB)*HH + y0+yy)*WW + xx;
        *(float2*)&out[o2] = make_float2(acc[nt][2], acc[nt][3]);
    }
}

// ------- 7x1 conv via mma.sync: 7 y-shifted GEMM passes, ci-chunked ----------
// Block = (b, 2 y-rows); grid (16, B). Xt[256 rows = 8y-halo x 32x][64 ci]
// hi/lo (144B rows); Wk[128co][64ci] hi/lo per (kh, cc) from g_w71t.
// Row shift = n + 32*kh. Fused slot stats.
__global__ void __launch_bounds__(256, 2) c7x1_mma_kernel(const float* __restrict__ in,
                                                          float* __restrict__ out,
                                                          int oslot) {
    extern __shared__ __align__(16) char dsm[];
    const uint32_t oXlo = 36864u, oWhi = 73728u, oWlo = 92160u;  // total 110592
    int tid = threadIdx.x, lane = tid & 31, wid = tid >> 5;
    int tile = blockIdx.x, b = blockIdx.y;
    int y0 = tile * 2;
    uint32_t sbase = smem_u32(dsm);

    float acc[8][4];
    #pragma unroll
    for (int nt = 0; nt < 8; nt++)
        #pragma unroll
        for (int q = 0; q < 4; q++) acc[nt][q] = 0.f;

    uint32_t arowoff = (uint32_t)(wid*16 + (lane & 15))*144u + (uint32_t)(lane >> 4)*16u;
    uint32_t l8 = (uint32_t)(lane & 7);
    uint32_t bhalf = (uint32_t)((lane >> 3) & 1) * 16u;

    for (int cc = 0; cc < CP; cc += 64) {
        __syncthreads();                       // previous mma done before X refill
        // fill Xt hi/lo: 256 rows (yy 0..7 -> y = y0+yy-3) x 64 ci
        for (int i = tid; i < 16384; i += 256) {
            int ci = i >> 8, r = i & 255;
            int yy = r >> 5, xx = r & 31;
            int y = y0 + yy - 3;
            float v = 0.f;
            if (y >= 0 && y < HH) v = in[(((size_t)b*CP + cc+ci)*HH + y)*WW + xx];
            __nv_bfloat16 h, l; bf16_split(v, h, l);
            uint32_t off = (uint32_t)r*144u + (uint32_t)ci*2u;
            *(__nv_bfloat16*)(dsm + off) = h;
            *(__nv_bfloat16*)(dsm + oXlo + off) = l;
        }
        for (int kh = 0; kh < 7; kh++) {
            __syncthreads();                   // X fill / previous mma done
            const float* wsrc = g_w71t + kh*16384;
            for (int i = tid; i < 2048; i += 256) {  // float4 units: 128co x 16
                int co = i >> 4, c0 = (i & 15) << 2;
                float4 v = *(const float4*)&wsrc[(co << 7) + cc + c0];
                __nv_bfloat16 h0,h1,h2,h3,l0,l1,l2,l3;
                bf16_split(v.x,h0,l0); bf16_split(v.y,h1,l1);
                bf16_split(v.z,h2,l2); bf16_split(v.w,h3,l3);
                uint32_t off = (uint32_t)co*144u + (uint32_t)c0*2u;
                *(uint32_t*)(dsm + oWhi + off)     = ((uint32_t)__bfloat16_as_ushort(h1)<<16) | __bfloat16_as_ushort(h0);
                *(uint32_t*)(dsm + oWhi + off + 4) = ((uint32_t)__bfloat16_as_ushort(h3)<<16) | __bfloat16_as_ushort(h2);
                *(uint32_t*)(dsm + oWlo + off)     = ((uint32_t)__bfloat16_as_ushort(l1)<<16) | __bfloat16_as_ushort(l0);
                *(uint32_t*)(dsm + oWlo + off + 4) = ((uint32_t)__bfloat16_as_ushort(l3)<<16) | __bfloat16_as_ushort(l2);
            }
            __syncthreads();
            #pragma unroll
            for (int pass = 0; pass < 3; pass++) {
                uint32_t aaddr = sbase + (pass == 2 ? oWlo : oWhi) + arowoff;
                uint32_t xoff  = (pass == 1) ? oXlo : 0u;
                #pragma unroll
                for (int kc = 0; kc < 4; kc++) {
                    uint32_t a0,a1,a2,a3;
                    ldsm_x4(a0,a1,a2,a3, aaddr + (uint32_t)kc*32u);
                    #pragma unroll
                    for (int nt = 0; nt < 8; nt++) {
                        uint32_t row = (uint32_t)(nt*8) + l8 + (uint32_t)(kh*32);
                        uint32_t b0,b1;
                        ldsm_x2(b0,b1, sbase + xoff + row*144u + (uint32_t)kc*32u + bhalf);
                        mma_bf16(acc[nt][0],acc[nt][1],acc[nt][2],acc[nt][3], a0,a1,a2,a3, b0,b1);
                    }
                }
            }
        }
    }

    int coA = wid*16 + (lane >> 2);
    int coB = coA + 8;
    float sA=0.f, sA2=0.f, sB=0.f, sB2=0.f;
    #pragma unroll
    for (int nt = 0; nt < 8; nt++) {
        int n = nt*8 + (lane & 3)*2;
        int yy = n >> 5, xx = n & 31;
        *(float2*)&out[(((size_t)b*CP + coA)*HH + y0+yy)*WW + xx] = make_float2(acc[nt][0], acc[nt][1]);
        *(float2*)&out[(((size_t)b*CP + coB)*HH + y0+yy)*WW + xx] = make_float2(acc[nt][2], acc[nt][3]);
        sA += acc[nt][0] + acc[nt][1]; sA2 += acc[nt][0]*acc[nt][0] + acc[nt][1]*acc[nt][1];
        sB += acc[nt][2] + acc[nt][3]; sB2 += acc[nt][2]*acc[nt][2] + acc[nt][3]*acc[nt][3];
    }
    #pragma unroll
    for (int o = 1; o < 4; o <<= 1) {
        sA  += __shfl_xor_sync(0xffffffffu, sA,  o);
        sA2 += __shfl_xor_sync(0xffffffffu, sA2, o);
        sB  += __shfl_xor_sync(0xffffffffu, sB,  o);
        sB2 += __shfl_xor_sync(0xffffffffu, sB2, o);
    }
    if ((lane & 3) == 0 && oslot >= 0) {
        atomicAdd(&g_ssum [oslot*CP + coA], (double)sA);
        atomicAdd(&g_ssum2[oslot*CP + coA], (double)sA2);
        atomicAdd(&g_ssum [oslot*CP + coB], (double)sB);
        atomicAdd(&g_ssum2[oslot*CP + coB], (double)sB2);
    }
}

// ---------------- final combine + scatter (float4) ----------------------------
__global__ void combine_kernel(const float* __restrict__ wv, float* __restrict__ out) {
    int n4 = blockIdx.x * 256 + threadIdx.x;   // < NSEL/4
    int n = n4 << 2;
    int b = n >> 17, p = (n >> 10) & 127, hw = n & 1023;
    float m0 = g_meanv[0*CP+p],  r0 = g_rstdv[0*CP+p];
    float m1 = g_meanv[1*CP+p],  r1 = g_rstdv[1*CP+p];
    float m3 = g_meanv[3*CP+p],  r3 = g_rstdv[3*CP+p];
    float m5 = g_meanv[5*CP+p],  r5 = g_rstdv[5*CP+p];
    float m7 = g_meanv[7*CP+p],  r7 = g_rstdv[7*CP+p];
    float m8 = g_meanv[8*CP+p],  r8 = g_rstdv[8*CP+p];
    float m9 = g_meanv[9*CP+p],  r9 = g_rstdv[9*CP+p];
    float mA = g_meanv[10*CP+p], rA = g_rstdv[10*CP+p];
    float w1=wv[1],w2=wv[2],w3=wv[3],w4=wv[4],w5=wv[5],w6=wv[6],w7=wv[7],w8=wv[8],w9=wv[9];
    float a[4] = {0.f,0.f,0.f,0.f};
    { float4 v = *(const float4*)&g_bmax[n];  const float* q=(const float*)&v;
      #pragma unroll
      for (int t=0;t<4;t++) a[t] += w1*(q[t]-m0)*r0; }
    { float4 v = *(const float4*)&g_bavg[n];  const float* q=(const float*)&v;
      #pragma unroll
      for (int t=0;t<4;t++) a[t] += w2*(q[t]-m1)*r1; }
    { float4 v = *(const float4*)&g_xtemp[n]; const float* q=(const float*)&v;
      #pragma unroll
      for (int t=0;t<4;t++) a[t] += w3*q[t]; }
    { float4 v = *(const float4*)&g_s3[n];    const float* q=(const float*)&v;
      #pragma unroll
      for (int t=0;t<4;t++) a[t] += w4*(q[t]-m3)*r3; }
    { float4 v = *(const float4*)&g_s5[n];    const float* q=(const float*)&v;
      #pragma unroll
      for (int t=0;t<4;t++) a[t] += w5*(q[t]-m5)*r5; }
    { float4 v = *(const float4*)&g_s7[n];    const float* q=(const float*)&v;
      #pragma unroll
      for (int t=0;t<4;t++) a[t] += w6*(q[t]-m7)*r7; }
    { float4 v = *(const float4*)&g_d3[n];    const float* q=(const float*)&v;
      #pragma unroll
      for (int t=0;t<4;t++) a[t] += w7*(q[t]-m8)*r8; }
    { float4 v = *(const float4*)&g_d5[n];    const float* q=(const float*)&v;
      #pragma unroll
      for (int t=0;t<4;t++) a[t] += w8*(q[t]-m9)*r9; }
    { float4 v = *(const float4*)&g_c7[n];    const float* q=(const float*)&v;
      #pragma unroll
      for (int t=0;t<4;t++) a[t] += w9*(q[t]-mA)*rA; }
    int cs = g_idx[p];
    *(float4*)&out[(((size_t)b*C + cs) << 10) + hw] = make_float4(a[0],a[1],a[2],a[3]);
}

// =============================================================================
extern "C" void kernel_launch(void* const* d_in, const int* in_sizes, int n_in,
                              void* d_out, int out_size) {
    const float* x        = (const float*)d_in[0];
    const float* weights  = (const float*)d_in[1];
    const float* wall     = (const float*)d_in[2];
    const float* w_fc1    = (const float*)d_in[3];
    const float* w_fc2    = (const float*)d_in[4];
    const float* sep3_dw1 = (const float*)d_in[5];
    const float* sep3_pw1 = (const float*)d_in[6];
    const float* sep3_dw2 = (const float*)d_in[7];
    const float* sep3_pw2 = (const float*)d_in[8];
    const float* sep5_dw1 = (const float*)d_in[9];
    const float* sep5_pw1 = (const float*)d_in[10];
    const float* sep5_dw2 = (const float*)d_in[11];
    const float* sep5_pw2 = (const float*)d_in[12];
    const float* sep7_dw1 = (const float*)d_in[13];
    const float* sep7_pw1 = (const float*)d_in[14];
    const float* sep7_dw2 = (const float*)d_in[15];
    const float* sep7_pw2 = (const float*)d_in[16];
    const float* dil3_dw  = (const float*)d_in[17];
    const float* dil3_pw  = (const float*)d_in[18];
    const float* dil5_dw  = (const float*)d_in[19];
    const float* dil5_pw  = (const float*)d_in[20];
    const float* w_1x7    = (const float*)d_in[21];
    const float* w_7x1    = (const float*)d_in[22];
    float* out = (float*)d_out;

    // Resolve REAL device addresses (host shadow symbols are ATS garbage on GB300).
    float *t_1,*t_2,*t_bmax,*t_bavg,*t_s3,*t_s5,*t_s7,*t_d3,*t_d5,*t_c7;
    { void* p;
      cudaGetSymbolAddress(&p, g_t1);    t_1    =(float*)p;
      cudaGetSymbolAddress(&p, g_t2);    t_2    =(float*)p;
      cudaGetSymbolAddress(&p, g_bmax);  t_bmax =(float*)p;
      cudaGetSymbolAddress(&p, g_bavg);  t_bavg =(float*)p;
      cudaGetSymbolAddress(&p, g_s3);    t_s3   =(float*)p;
      cudaGetSymbolAddress(&p, g_s5);    t_s5   =(float*)p;
      cudaGetSymbolAddress(&p, g_s7);    t_s7   =(float*)p;
      cudaGetSymbolAddress(&p, g_d3);    t_d3   =(float*)p;
      cudaGetSymbolAddress(&p, g_d5);    t_d5   =(float*)p;
      cudaGetSymbolAddress(&p, g_c7);    t_c7   =(float*)p; }

    const int SMPW  = 106496;                     // pw: W hi/lo + X hi/lo
    const int SMC17 = 110976;                     // c1x7: Xt hi/lo + Wk hi/lo
    const int SMC71 = 110592;                     // c7x1: Xt hi/lo + Wk hi/lo
    cudaFuncSetAttribute(pw_mma_kernel,   cudaFuncAttributeMaxDynamicSharedMemorySize, SMPW);
    cudaFuncSetAttribute(c1x7_mma_kernel, cudaFuncAttributeMaxDynamicSharedMemorySize, SMC17);
    cudaFuncSetAttribute(c7x1_mma_kernel, cudaFuncAttributeMaxDynamicSharedMemorySize, SMC71);

    const int GSEL4 = NSEL / 1024;   // 8192
    const int GALL4 = NALL / 1024;   // 32768
    dim3 gpw(16, B);                 // pw + 7-convs: 16 spatial tiles x 64 batches
    const int GDW = B * CP;          // 8192

    // prefix (launch index 3 = c1x7_mma -> gets ncu-sampled)
    attn_fused_kernel<<<B, 512>>>(x, w_fc1, wall, w_fc2);
    slist_topk_kernel<<<1, C>>>();
    transw_kernel<<<(7*CP*CP + 255)/256, 256>>>(w_1x7, w_7x1);

    // 1x7 (gathers from x) -> 7x1 (slot 10), both on tensor cores
    c1x7_mma_kernel<<<gpw, 256, SMC17>>>(x, t_1);                 // <- PROFILED
    c7x1_mma_kernel<<<gpw, 256, SMC71>>>(t_1, t_c7, 10);

    // sep3 (dw gathers from x directly)
    dw_conv_kernel<3,1,1,1><<<GDW, 256>>>(x, t_1, sep3_dw1, 0);
    pw_mma_kernel<<<gpw, 256, SMPW>>>(t_1, t_2, sep3_pw1, 2);
    dw_conv_kernel<3,1,2,0><<<GDW, 256>>>(t_2, t_1, sep3_dw2, 2);
    pw_mma_kernel<<<gpw, 256, SMPW>>>(t_1, t_s3, sep3_pw2, 3);

    // sep5
    dw_conv_kernel<5,1,1,1><<<GDW, 256>>>(x, t_1, sep5_dw1, 0);
    pw_mma_kernel<<<gpw, 256, SMPW>>>(t_1, t_2, sep5_pw1, 4);
    dw_conv_kernel<5,1,2,0><<<GDW, 256>>>(t_2, t_1, sep5_dw2, 4);
    pw_mma_kernel<<<gpw, 256, SMPW>>>(t_1, t_s5, sep5_pw2, 5);

    // sep7
    dw_conv_kernel<7,1,1,1><<<GDW, 256>>>(x, t_1, sep7_dw1, 0);
    pw_mma_kernel<<<gpw, 256, SMPW>>>(t_1, t_2, sep7_pw1, 6);
    dw_conv_kernel<7,1,2,0><<<GDW, 256>>>(t_2, t_1, sep7_dw2, 6);
    pw_mma_kernel<<<gpw, 256, SMPW>>>(t_1, t_s7, sep7_pw2, 7);

    // dilated
    dw_conv_kernel<3,2,1,1><<<GDW, 256>>>(x, t_1, dil3_dw, 0);
    pw_mma_kernel<<<gpw, 256, SMPW>>>(t_1, t_d3, dil3_pw, 8);
    dw_conv_kernel<5,2,1,1><<<GDW, 256>>>(x, t_1, dil5_dw, 0);
    pw_mma_kernel<<<gpw, 256, SMPW>>>(t_1, t_d5, dil5_pw, 9);

    // independent passes
    gather4_kernel<<<GSEL4, 256>>>(x);
    scale4_kernel<<<GALL4, 256>>>(x, out);
    pool3f_kernel<<<GDW, 256>>>(x, t_bmax, t_bavg);

    // finalize all stats, combine, scatter
    finalize_kernel<<<NSLOT, 128>>>();
    combine_kernel<<<GSEL4, 256>>>(weights, out);
}